// round 2
// baseline (speedup 1.0000x reference)
#include <cuda_runtime.h>
#include <math.h>

#define Bq 4
#define Wd 2048
#define DM 256
#define DI 512
#define DS 16
#define DR 16
#define NROW (Bq*Wd)   // 8192

// ---------------- static scratch ----------------
__device__ float g_u[NROW*DM];        // rms-normed input
__device__ float g_xz[NROW*2*DI];     // in_proj output
__device__ float g_xs[NROW*DI];       // conv+silu output (u for scan)
__device__ float g_dbc[NROW*48];      // x_proj output
__device__ float g_delta[NROW*DI];    // softplus(dt)
__device__ float g_y[NROW*DI];        // scan output (gated)

__device__ __forceinline__ void ffma2(unsigned long long& d,
                                      unsigned long long a,
                                      unsigned long long b) {
    asm("fma.rn.f32x2 %0, %1, %2, %0;" : "+l"(d) : "l"(a), "l"(b));
}

// ---------------- embed ----------------
__global__ void k_embed(const float* __restrict__ x, const float* __restrict__ ew,
                        const float* __restrict__ eb, float* __restrict__ h) {
    int r = blockIdx.x, d = threadIdx.x;
    h[r*DM + d] = fmaf(x[r], ew[d], eb[d]);
}

// ---------------- rmsnorm -> g_u ----------------
__global__ void k_rmsnorm(const float* __restrict__ h, const float* __restrict__ w) {
    int r = blockIdx.x, d = threadIdx.x;
    float v = h[r*DM + d];
    float ss = v*v;
    #pragma unroll
    for (int o = 16; o; o >>= 1) ss += __shfl_xor_sync(0xffffffffu, ss, o);
    __shared__ float sh[8];
    int wid = d >> 5, lane = d & 31;
    if (lane == 0) sh[wid] = ss;
    __syncthreads();
    if (wid == 0) {
        float t = (lane < 8) ? sh[lane] : 0.f;
        #pragma unroll
        for (int o = 4; o; o >>= 1) t += __shfl_xor_sync(0xffffffffu, t, o);
        if (lane == 0) sh[0] = t;
    }
    __syncthreads();
    float inv = rsqrtf(sh[0] * (1.0f/DM) + 1e-5f);
    g_u[r*DM + d] = v * inv * w[d];
}

// ---------------- f32x2 SGEMM: C[m,n] (+)= sum_k A[m,k]*Wt[n,k] ----------------
// BM=128, BK=8, TM=8 fixed. A stored DUPLICATED in smem so (a,a) pairs are
// direct 8B loads; B pairs are consecutive n. Double-buffered.
template<int BN, int TN, bool ACC>
__global__ __launch_bounds__(256) void k_gemm2(
    const float* __restrict__ A, const float* __restrict__ Wt,
    float* __restrict__ C, int M, int N, int K)
{
    constexpr int BM = 128, BK = 8, TM = 8;
    constexpr int ASTR = 2*BM + 8;     // 264 floats: 16B-aligned rows, conflict-spread
    constexpr int BSTR = BN + 4;
    __shared__ float As[2][BK][ASTR];
    __shared__ float Bs[2][BK][BSTR];

    const int tid = threadIdx.x;
    const int tc = tid % (BN/TN);
    const int tr = tid / (BN/TN);
    const int m0 = blockIdx.y * BM, n0 = blockIdx.x * BN;

    // loader indices
    const int am = tid >> 1;             // 0..127
    const int ak = (tid & 1) * 4;        // 0 or 4

    unsigned long long acc[TM][TN/2];
    #pragma unroll
    for (int i = 0; i < TM; i++)
        #pragma unroll
        for (int j = 0; j < TN/2; j++) acc[i][j] = 0ull;

    const int nk = K / BK;

    // prologue: load block 0
    {
        float4 va = *(const float4*)&A[(size_t)(m0+am)*K + ak];
        *(float2*)&As[0][ak+0][2*am] = make_float2(va.x, va.x);
        *(float2*)&As[0][ak+1][2*am] = make_float2(va.y, va.y);
        *(float2*)&As[0][ak+2][2*am] = make_float2(va.z, va.z);
        *(float2*)&As[0][ak+3][2*am] = make_float2(va.w, va.w);
        if (BN == 128) {
            int bn = tid >> 1, bk = (tid & 1) * 4;
            float4 vb = *(const float4*)&Wt[(size_t)(n0+bn)*K + bk];
            Bs[0][bk+0][bn] = vb.x; Bs[0][bk+1][bn] = vb.y;
            Bs[0][bk+2][bn] = vb.z; Bs[0][bk+3][bn] = vb.w;
        } else {
            int bn = tid >> 2, bk = (tid & 3) * 2;
            float2 vb = *(const float2*)&Wt[(size_t)(n0+bn)*K + bk];
            Bs[0][bk+0][bn] = vb.x; Bs[0][bk+1][bn] = vb.y;
        }
    }
    __syncthreads();

    for (int kb = 0; kb < nk; kb++) {
        const int buf = kb & 1;
        float4 va, vb4; float2 vb2;
        const bool more = (kb + 1 < nk);
        if (more) {
            int k0 = (kb+1) * BK;
            va = *(const float4*)&A[(size_t)(m0+am)*K + k0 + ak];
            if (BN == 128) {
                int bn = tid >> 1, bk = (tid & 1) * 4;
                vb4 = *(const float4*)&Wt[(size_t)(n0+bn)*K + k0 + bk];
            } else {
                int bn = tid >> 2, bk = (tid & 3) * 2;
                vb2 = *(const float2*)&Wt[(size_t)(n0+bn)*K + k0 + bk];
            }
        }

        #pragma unroll
        for (int kk = 0; kk < BK; kk++) {
            unsigned long long a2[TM];
            const ulonglong2* pa = (const ulonglong2*)&As[buf][kk][2*tr*TM];
            ulonglong2 t0 = pa[0], t1 = pa[1], t2 = pa[2], t3 = pa[3];
            a2[0]=t0.x; a2[1]=t0.y; a2[2]=t1.x; a2[3]=t1.y;
            a2[4]=t2.x; a2[5]=t2.y; a2[6]=t3.x; a2[7]=t3.y;
            unsigned long long b2[TN/2];
            const ulonglong2* pb = (const ulonglong2*)&Bs[buf][kk][tc*TN];
            if (TN == 8) {
                ulonglong2 u0 = pb[0], u1 = pb[1];
                b2[0]=u0.x; b2[1]=u0.y; b2[2]=u1.x; b2[3]=u1.y;
            } else {
                ulonglong2 u0 = pb[0];
                b2[0]=u0.x; b2[1]=u0.y;
            }
            #pragma unroll
            for (int i = 0; i < TM; i++)
                #pragma unroll
                for (int j = 0; j < TN/2; j++)
                    ffma2(acc[i][j], a2[i], b2[j]);
        }

        if (more) {
            int nb = buf ^ 1;
            *(float2*)&As[nb][ak+0][2*am] = make_float2(va.x, va.x);
            *(float2*)&As[nb][ak+1][2*am] = make_float2(va.y, va.y);
            *(float2*)&As[nb][ak+2][2*am] = make_float2(va.z, va.z);
            *(float2*)&As[nb][ak+3][2*am] = make_float2(va.w, va.w);
            if (BN == 128) {
                int bn = tid >> 1, bk = (tid & 1) * 4;
                Bs[nb][bk+0][bn] = vb4.x; Bs[nb][bk+1][bn] = vb4.y;
                Bs[nb][bk+2][bn] = vb4.z; Bs[nb][bk+3][bn] = vb4.w;
            } else {
                int bn = tid >> 2, bk = (tid & 3) * 2;
                Bs[nb][bk+0][bn] = vb2.x; Bs[nb][bk+1][bn] = vb2.y;
            }
        }
        __syncthreads();
    }

    // epilogue
    #pragma unroll
    for (int i = 0; i < TM; i++) {
        size_t rbase = (size_t)(m0 + tr*TM + i)*N + n0 + tc*TN;
        #pragma unroll
        for (int j = 0; j < TN/2; j++) {
            float2 v = *(float2*)&acc[i][j];
            float* p = &C[rbase + 2*j];
            if (ACC) { p[0] += v.x; p[1] += v.y; }
            else     { p[0] = v.x;  p[1] = v.y; }
        }
    }
}

// ---------------- causal depthwise conv (k=4) + silu -> g_xs ----------------
__global__ void k_conv(const float* __restrict__ cw, const float* __restrict__ cb) {
    int idx = blockIdx.x * blockDim.x + threadIdx.x;
    int e = idx % DI;
    int row = idx / DI;
    int w = row % Wd;
    float acc = cb[e];
    #pragma unroll
    for (int k = 0; k < 4; k++) {
        int ww = w + k - 3;
        if (ww >= 0) acc = fmaf(cw[e*4 + k], g_xz[(size_t)(row + k - 3)*(2*DI) + e], acc);
    }
    g_xs[idx] = acc / (1.f + __expf(-acc));
}

// ---------------- x_proj ----------------
__global__ __launch_bounds__(256) void k_xproj(const float* __restrict__ xpw) {
    __shared__ float sx[8][DI];
    int r0 = blockIdx.x * 8;
    #pragma unroll
    for (int i = 0; i < 4; i++) {
        int idx = threadIdx.x + 256*i;
        int rr = idx / (DI/4);
        int c4 = idx % (DI/4);
        *(float4*)&sx[rr][c4*4] = *(const float4*)&g_xs[(size_t)(r0+rr)*DI + c4*4];
    }
    __syncthreads();
    int warp = threadIdx.x >> 5, lane = threadIdx.x & 31;
    for (int jj = 0; jj < 6; jj++) {
        int j = warp*6 + jj;
        float wreg[16];
        #pragma unroll
        for (int i = 0; i < 16; i++) wreg[i] = xpw[(size_t)j*DI + lane + 32*i];
        #pragma unroll
        for (int rr = 0; rr < 8; rr++) {
            float s = 0.f;
            #pragma unroll
            for (int i = 0; i < 16; i++) s = fmaf(wreg[i], sx[rr][lane + 32*i], s);
            #pragma unroll
            for (int o = 16; o; o >>= 1) s += __shfl_xor_sync(0xffffffffu, s, o);
            if (lane == 0) g_dbc[(size_t)(r0+rr)*48 + j] = s;
        }
    }
}

// ---------------- dt_proj + softplus ----------------
__global__ void k_dt(const float* __restrict__ dtw, const float* __restrict__ dtb) {
    int r = blockIdx.x, d = threadIdx.x;
    __shared__ float sd[DR];
    if (d < DR) sd[d] = g_dbc[(size_t)r*48 + d];
    __syncthreads();
    float acc = dtb[d];
    #pragma unroll
    for (int j = 0; j < DR; j++) acc = fmaf(sd[j], dtw[d*DR + j], acc);
    float e = __expf(-fabsf(acc));
    float sp = fmaxf(acc, 0.f) + __logf(1.f + e);
    g_delta[(size_t)r*DI + d] = sp;
}

// ---------------- selective scan (gate fused) ----------------
__global__ __launch_bounds__(128) void k_scan(const float* __restrict__ A_log,
                                              const float* __restrict__ Dp) {
    int gw = (blockIdx.x * blockDim.x + threadIdx.x) >> 5;
    int lane = threadIdx.x & 31;
    int b = gw >> 8;
    int dpair = gw & 255;
    int s = lane & 15;
    int dd = dpair*2 + (lane >> 4);

    float Av = -expf(A_log[dd*DS + s]);
    float Dpv = Dp[dd];
    float hst = 0.f;

    const float* pd = g_delta + (size_t)b*Wd*DI + dd;
    const float* pu = g_xs    + (size_t)b*Wd*DI + dd;
    const float* pB = g_dbc   + (size_t)b*Wd*48 + DR + s;
    const float* pC = g_dbc   + (size_t)b*Wd*48 + DR + DS + s;
    const float* pz = g_xz    + (size_t)b*Wd*(2*DI) + DI + dd;
    float* py = g_y + (size_t)b*Wd*DI + dd;

    float dlt = pd[0], uu = pu[0], Bv = pB[0], Cv = pC[0], zv = pz[0];
    for (int t = 0; t < Wd; t++) {
        float dc = dlt, uc = uu, Bc = Bv, Cc = Cv, zc = zv;
        if (t + 1 < Wd) {
            dlt = pd[(size_t)(t+1)*DI];
            uu  = pu[(size_t)(t+1)*DI];
            Bv  = pB[(size_t)(t+1)*48];
            Cv  = pC[(size_t)(t+1)*48];
            zv  = pz[(size_t)(t+1)*(2*DI)];
        }
        float dA = __expf(dc * Av);
        hst = fmaf(dA, hst, dc * Bc * uc);
        float yv = hst * Cc;
        yv += __shfl_xor_sync(0xffffffffu, yv, 8);
        yv += __shfl_xor_sync(0xffffffffu, yv, 4);
        yv += __shfl_xor_sync(0xffffffffu, yv, 2);
        yv += __shfl_xor_sync(0xffffffffu, yv, 1);
        if (s == 0) {
            float g = zc / (1.f + __expf(-zc));
            py[(size_t)t*DI] = fmaf(uc, Dpv, yv) * g;
        }
    }
}

// ---------------- host launch ----------------
extern "C" void kernel_launch(void* const* d_in, const int* in_sizes, int n_in,
                              void* d_out, int out_size) {
    const float* x         = (const float*)d_in[0];
    const float* emb_w     = (const float*)d_in[1];
    const float* emb_b     = (const float*)d_in[2];
    const float* in_proj_w = (const float*)d_in[3];
    const float* conv_w    = (const float*)d_in[4];
    const float* conv_b    = (const float*)d_in[5];
    const float* x_proj_w  = (const float*)d_in[6];
    const float* dt_proj_w = (const float*)d_in[7];
    const float* dt_proj_b = (const float*)d_in[8];
    const float* A_log     = (const float*)d_in[9];
    const float* Dp        = (const float*)d_in[10];
    const float* out_proj_w= (const float*)d_in[11];
    const float* norm_w    = (const float*)d_in[12];
    float* h = (float*)d_out;

    float *p_u, *p_xz, *p_y;
    cudaGetSymbolAddress((void**)&p_u,  g_u);
    cudaGetSymbolAddress((void**)&p_xz, g_xz);
    cudaGetSymbolAddress((void**)&p_y,  g_y);

    k_embed<<<NROW, DM>>>(x, emb_w, emb_b, h);

    for (int l = 0; l < 2; ++l) {
        const float* inw = in_proj_w + (size_t)l * (2*DI) * DM;
        const float* cw  = conv_w   + (size_t)l * DI * 4;
        const float* cb  = conv_b   + (size_t)l * DI;
        const float* xpw = x_proj_w + (size_t)l * 48 * DI;
        const float* dtw = dt_proj_w+ (size_t)l * DI * DR;
        const float* dtb = dt_proj_b+ (size_t)l * DI;
        const float* al  = A_log    + (size_t)l * DI * DS;
        const float* dp  = Dp       + (size_t)l * DI;
        const float* ow  = out_proj_w + (size_t)l * DM * DI;
        const float* nw  = norm_w   + (size_t)l * DM;

        k_rmsnorm<<<NROW, DM>>>(h, nw);

        // xz = u @ in_w^T : M=8192, N=1024, K=256
        {
            dim3 grid((2*DI)/128, NROW/128);
            k_gemm2<128,8,false><<<grid, 256>>>(p_u, inw, p_xz, NROW, 2*DI, DM);
        }

        k_conv<<<(NROW*DI)/256, 256>>>(cw, cb);
        k_xproj<<<NROW/8, 256>>>(xpw);
        k_dt<<<NROW, DI>>>(dtw, dtb);
        k_scan<<<(Bq*(DI/2)*32)/128, 128>>>(al, dp);

        // h += y @ ow^T : M=8192, N=256, K=512
        {
            dim3 grid(DM/64, NROW/128);
            k_gemm2<64,4,true><<<grid, 256>>>(p_y, ow, h, NROW, DM, DI);
        }
    }
}

// round 3
// speedup vs baseline: 1.0972x; 1.0972x over previous
#include <cuda_runtime.h>
#include <math.h>

#define Bq 4
#define Wd 2048
#define DM 256
#define DI 512
#define DS 16
#define DR 16
#define NROW (Bq*Wd)   // 8192

// ---------------- static scratch ----------------
__device__ float g_u[NROW*DM];        // rms-normed input
__device__ float g_xz[NROW*2*DI];     // in_proj output
__device__ float g_xs[NROW*DI];       // conv+silu output
__device__ float g_dbc[NROW*48];      // x_proj output
__device__ float g_delta[NROW*DI];    // softplus(dt)
__device__ float g_y[NROW*DI];        // scan output (gated)

// ---------------- embed ----------------
__global__ void k_embed(const float* __restrict__ x, const float* __restrict__ ew,
                        const float* __restrict__ eb, float* __restrict__ h) {
    int r = blockIdx.x, d = threadIdx.x;
    h[r*DM + d] = fmaf(x[r], ew[d], eb[d]);
}

// ---------------- rmsnorm -> g_u ----------------
__global__ void k_rmsnorm(const float* __restrict__ h, const float* __restrict__ w) {
    int r = blockIdx.x, d = threadIdx.x;
    float v = h[r*DM + d];
    float ss = v*v;
    #pragma unroll
    for (int o = 16; o; o >>= 1) ss += __shfl_xor_sync(0xffffffffu, ss, o);
    __shared__ float sh[8];
    int wid = d >> 5, lane = d & 31;
    if (lane == 0) sh[wid] = ss;
    __syncthreads();
    if (wid == 0) {
        float t = (lane < 8) ? sh[lane] : 0.f;
        #pragma unroll
        for (int o = 4; o; o >>= 1) t += __shfl_xor_sync(0xffffffffu, t, o);
        if (lane == 0) sh[0] = t;
    }
    __syncthreads();
    float inv = rsqrtf(sh[0] * (1.0f/DM) + 1e-5f);
    g_u[r*DM + d] = v * inv * w[d];
}

// ---------------- SGEMM (plain FFMA, double-buffered): C[m,n] (+)= A[m,:]·Wt[n,:] ----
// BM=128, BK=8 fixed. 256 threads. TM=8. BN/TN templated.
template<int BN, int TN, bool ACC>
__global__ __launch_bounds__(256, 2) void k_gemm(
    const float* __restrict__ A, const float* __restrict__ Wt,
    float* __restrict__ C, int M, int N, int K)
{
    constexpr int BM = 128, BK = 8, TM = 8;
    constexpr int STR = 136;                 // padded row stride (floats)
    __shared__ float As[2][BK][STR];
    __shared__ float Bs[2][BK][STR];

    const int tid = threadIdx.x;
    const int tc = tid % (BN/TN);
    const int tr = tid / (BN/TN);
    const int m0 = blockIdx.y * BM, n0 = blockIdx.x * BN;

    const int am = tid >> 1;                 // 0..127
    const int ak = (tid & 1) * 4;            // 0 or 4
    const bool bldr = (BN == 128) || (tid < 128);
    const int bn = tid >> 1;                 // 0..127 (0..63 used when BN=64)
    const int bk = (tid & 1) * 4;

    float acc[TM][TN];
    #pragma unroll
    for (int i = 0; i < TM; i++)
        #pragma unroll
        for (int j = 0; j < TN; j++) acc[i][j] = 0.f;

    const int nk = K / BK;

    // prologue
    {
        float4 va = *(const float4*)&A[(size_t)(m0+am)*K + ak];
        As[0][ak+0][am] = va.x; As[0][ak+1][am] = va.y;
        As[0][ak+2][am] = va.z; As[0][ak+3][am] = va.w;
        if (bldr) {
            float4 vb = *(const float4*)&Wt[(size_t)(n0+bn)*K + bk];
            Bs[0][bk+0][bn] = vb.x; Bs[0][bk+1][bn] = vb.y;
            Bs[0][bk+2][bn] = vb.z; Bs[0][bk+3][bn] = vb.w;
        }
    }
    __syncthreads();

    for (int kb = 0; kb < nk; kb++) {
        const int buf = kb & 1;
        const bool more = (kb + 1 < nk);
        float4 va, vb;
        if (more) {
            int k0 = (kb+1) * BK;
            va = *(const float4*)&A[(size_t)(m0+am)*K + k0 + ak];
            if (bldr) vb = *(const float4*)&Wt[(size_t)(n0+bn)*K + k0 + bk];
        }

        #pragma unroll
        for (int kk = 0; kk < BK; kk++) {
            float a[TM], b[TN];
            float4 a0 = *(const float4*)&As[buf][kk][tr*TM];
            float4 a1 = *(const float4*)&As[buf][kk][tr*TM + 4];
            a[0]=a0.x; a[1]=a0.y; a[2]=a0.z; a[3]=a0.w;
            a[4]=a1.x; a[5]=a1.y; a[6]=a1.z; a[7]=a1.w;
            float4 b0 = *(const float4*)&Bs[buf][kk][tc*TN];
            b[0]=b0.x; b[1]=b0.y; b[2]=b0.z; b[3]=b0.w;
            if (TN == 8) {
                float4 b1 = *(const float4*)&Bs[buf][kk][tc*TN + 4];
                b[4]=b1.x; b[5]=b1.y; b[6]=b1.z; b[7]=b1.w;
            }
            #pragma unroll
            for (int i = 0; i < TM; i++)
                #pragma unroll
                for (int j = 0; j < TN; j++)
                    acc[i][j] = fmaf(a[i], b[j], acc[i][j]);
        }

        if (more) {
            int nb = buf ^ 1;
            As[nb][ak+0][am] = va.x; As[nb][ak+1][am] = va.y;
            As[nb][ak+2][am] = va.z; As[nb][ak+3][am] = va.w;
            if (bldr) {
                Bs[nb][bk+0][bn] = vb.x; Bs[nb][bk+1][bn] = vb.y;
                Bs[nb][bk+2][bn] = vb.z; Bs[nb][bk+3][bn] = vb.w;
            }
        }
        __syncthreads();
    }

    // epilogue (float4 stores)
    #pragma unroll
    for (int i = 0; i < TM; i++) {
        size_t rbase = (size_t)(m0 + tr*TM + i)*N + n0 + tc*TN;
        #pragma unroll
        for (int j4 = 0; j4 < TN/4; j4++) {
            float4* p = (float4*)&C[rbase + 4*j4];
            float4 v = make_float4(acc[i][4*j4+0], acc[i][4*j4+1],
                                   acc[i][4*j4+2], acc[i][4*j4+3]);
            if (ACC) {
                float4 o = *p;
                v.x += o.x; v.y += o.y; v.z += o.z; v.w += o.w;
            }
            *p = v;
        }
    }
}

// ---------------- causal depthwise conv (k=4) + silu, float4 ----------------
__global__ void k_conv(const float* __restrict__ cw, const float* __restrict__ cb) {
    int idx = blockIdx.x * blockDim.x + threadIdx.x;   // NROW*DI/4
    int e4 = idx % (DI/4);
    int row = idx / (DI/4);
    int w = row % Wd;
    int e = e4 * 4;

    float4 acc = *(const float4*)&cb[e];
    float4 w0 = *(const float4*)&cw[(e+0)*4];
    float4 w1 = *(const float4*)&cw[(e+1)*4];
    float4 w2 = *(const float4*)&cw[(e+2)*4];
    float4 w3 = *(const float4*)&cw[(e+3)*4];
    const float wk[4][4] = {{w0.x,w0.y,w0.z,w0.w},{w1.x,w1.y,w1.z,w1.w},
                            {w2.x,w2.y,w2.z,w2.w},{w3.x,w3.y,w3.z,w3.w}};
    #pragma unroll
    for (int k = 0; k < 4; k++) {
        int ww = w + k - 3;
        if (ww >= 0) {
            float4 xv = *(const float4*)&g_xz[(size_t)(row + k - 3)*(2*DI) + e];
            acc.x = fmaf(wk[0][k], xv.x, acc.x);
            acc.y = fmaf(wk[1][k], xv.y, acc.y);
            acc.z = fmaf(wk[2][k], xv.z, acc.z);
            acc.w = fmaf(wk[3][k], xv.w, acc.w);
        }
    }
    acc.x /= (1.f + __expf(-acc.x));
    acc.y /= (1.f + __expf(-acc.y));
    acc.z /= (1.f + __expf(-acc.z));
    acc.w /= (1.f + __expf(-acc.w));
    *(float4*)&g_xs[(size_t)row*DI + e] = acc;
}

// ---------------- x_proj ----------------
__global__ __launch_bounds__(256) void k_xproj(const float* __restrict__ xpw) {
    __shared__ float sx[8][DI];
    int r0 = blockIdx.x * 8;
    #pragma unroll
    for (int i = 0; i < 4; i++) {
        int idx = threadIdx.x + 256*i;
        int rr = idx / (DI/4);
        int c4 = idx % (DI/4);
        *(float4*)&sx[rr][c4*4] = *(const float4*)&g_xs[(size_t)(r0+rr)*DI + c4*4];
    }
    __syncthreads();
    int warp = threadIdx.x >> 5, lane = threadIdx.x & 31;
    for (int jj = 0; jj < 6; jj++) {
        int j = warp*6 + jj;
        float wreg[16];
        #pragma unroll
        for (int i = 0; i < 16; i++) wreg[i] = xpw[(size_t)j*DI + lane + 32*i];
        #pragma unroll
        for (int rr = 0; rr < 8; rr++) {
            float s = 0.f;
            #pragma unroll
            for (int i = 0; i < 16; i++) s = fmaf(wreg[i], sx[rr][lane + 32*i], s);
            #pragma unroll
            for (int o = 16; o; o >>= 1) s += __shfl_xor_sync(0xffffffffu, s, o);
            if (lane == 0) g_dbc[(size_t)(r0+rr)*48 + j] = s;
        }
    }
}

// ---------------- dt_proj + softplus ----------------
__global__ void k_dt(const float* __restrict__ dtw, const float* __restrict__ dtb) {
    int r = blockIdx.x, d = threadIdx.x;
    __shared__ float sd[DR];
    if (d < DR) sd[d] = g_dbc[(size_t)r*48 + d];
    __syncthreads();
    float acc = dtb[d];
    #pragma unroll
    for (int j = 0; j < DR; j++) acc = fmaf(sd[j], dtw[d*DR + j], acc);
    float e = __expf(-fabsf(acc));
    float sp = fmaxf(acc, 0.f) + __logf(1.f + e);
    g_delta[(size_t)r*DI + d] = sp;
}

// ---------------- selective scan (gate fused) ----------------
__global__ __launch_bounds__(128) void k_scan(const float* __restrict__ A_log,
                                              const float* __restrict__ Dp) {
    int gw = (blockIdx.x * blockDim.x + threadIdx.x) >> 5;
    int lane = threadIdx.x & 31;
    int b = gw >> 8;
    int dpair = gw & 255;
    int s = lane & 15;
    int dd = dpair*2 + (lane >> 4);

    float Av = -expf(A_log[dd*DS + s]);
    float Dpv = Dp[dd];
    float hst = 0.f;

    const float* pd = g_delta + (size_t)b*Wd*DI + dd;
    const float* pu = g_xs    + (size_t)b*Wd*DI + dd;
    const float* pB = g_dbc   + (size_t)b*Wd*48 + DR + s;
    const float* pC = g_dbc   + (size_t)b*Wd*48 + DR + DS + s;
    const float* pz = g_xz    + (size_t)b*Wd*(2*DI) + DI + dd;
    float* py = g_y + (size_t)b*Wd*DI + dd;

    float dlt = pd[0], uu = pu[0], Bv = pB[0], Cv = pC[0], zv = pz[0];
    for (int t = 0; t < Wd; t++) {
        float dc = dlt, uc = uu, Bc = Bv, Cc = Cv, zc = zv;
        if (t + 1 < Wd) {
            dlt = pd[(size_t)(t+1)*DI];
            uu  = pu[(size_t)(t+1)*DI];
            Bv  = pB[(size_t)(t+1)*48];
            Cv  = pC[(size_t)(t+1)*48];
            zv  = pz[(size_t)(t+1)*(2*DI)];
        }
        float dA = __expf(dc * Av);
        hst = fmaf(dA, hst, dc * Bc * uc);
        float yv = hst * Cc;
        yv += __shfl_xor_sync(0xffffffffu, yv, 8);
        yv += __shfl_xor_sync(0xffffffffu, yv, 4);
        yv += __shfl_xor_sync(0xffffffffu, yv, 2);
        yv += __shfl_xor_sync(0xffffffffu, yv, 1);
        if (s == 0) {
            float g = zc / (1.f + __expf(-zc));
            py[(size_t)t*DI] = fmaf(uc, Dpv, yv) * g;
        }
    }
}

// ---------------- host launch ----------------
extern "C" void kernel_launch(void* const* d_in, const int* in_sizes, int n_in,
                              void* d_out, int out_size) {
    const float* x         = (const float*)d_in[0];
    const float* emb_w     = (const float*)d_in[1];
    const float* emb_b     = (const float*)d_in[2];
    const float* in_proj_w = (const float*)d_in[3];
    const float* conv_w    = (const float*)d_in[4];
    const float* conv_b    = (const float*)d_in[5];
    const float* x_proj_w  = (const float*)d_in[6];
    const float* dt_proj_w = (const float*)d_in[7];
    const float* dt_proj_b = (const float*)d_in[8];
    const float* A_log     = (const float*)d_in[9];
    const float* Dp        = (const float*)d_in[10];
    const float* out_proj_w= (const float*)d_in[11];
    const float* norm_w    = (const float*)d_in[12];
    float* h = (float*)d_out;

    float *p_u, *p_xz, *p_y;
    cudaGetSymbolAddress((void**)&p_u,  g_u);
    cudaGetSymbolAddress((void**)&p_xz, g_xz);
    cudaGetSymbolAddress((void**)&p_y,  g_y);

    k_embed<<<NROW, DM>>>(x, emb_w, emb_b, h);

    for (int l = 0; l < 2; ++l) {
        const float* inw = in_proj_w + (size_t)l * (2*DI) * DM;
        const float* cw  = conv_w   + (size_t)l * DI * 4;
        const float* cb  = conv_b   + (size_t)l * DI;
        const float* xpw = x_proj_w + (size_t)l * 48 * DI;
        const float* dtw = dt_proj_w+ (size_t)l * DI * DR;
        const float* dtb = dt_proj_b+ (size_t)l * DI;
        const float* al  = A_log    + (size_t)l * DI * DS;
        const float* dp  = Dp       + (size_t)l * DI;
        const float* ow  = out_proj_w + (size_t)l * DM * DI;
        const float* nw  = norm_w   + (size_t)l * DM;

        k_rmsnorm<<<NROW, DM>>>(h, nw);

        // xz = u @ in_w^T : M=8192, N=1024, K=256
        {
            dim3 grid((2*DI)/128, NROW/128);
            k_gemm<128,8,false><<<grid, 256>>>(p_u, inw, p_xz, NROW, 2*DI, DM);
        }

        k_conv<<<(NROW*DI/4)/256, 256>>>(cw, cb);
        k_xproj<<<NROW/8, 256>>>(xpw);
        k_dt<<<NROW, DI>>>(dtw, dtb);
        k_scan<<<(Bq*(DI/2)*32)/128, 128>>>(al, dp);

        // h += y @ ow^T : M=8192, N=256, K=512
        {
            dim3 grid(DM/64, NROW/128);
            k_gemm<64,4,true><<<grid, 256>>>(p_y, ow, h, NROW, DM, DI);
        }
    }
}

// round 4
// speedup vs baseline: 1.6776x; 1.5290x over previous
#include <cuda_runtime.h>
#include <math.h>

#define Bq 4
#define Wd 2048
#define DM 256
#define DI 512
#define DS 16
#define DR 16
#define NROW (Bq*Wd)   // 8192

// ---------------- static scratch ----------------
__device__ float g_u[NROW*DM];
__device__ float g_xz[NROW*2*DI];
__device__ float g_xs[NROW*DI];
__device__ float g_dbc[NROW*48];
__device__ float g_delta[NROW*DI];
__device__ float g_y[NROW*DI];

// ---------------- embed ----------------
__global__ void k_embed(const float* __restrict__ x, const float* __restrict__ ew,
                        const float* __restrict__ eb, float* __restrict__ h) {
    int r = blockIdx.x, d = threadIdx.x;
    h[r*DM + d] = fmaf(x[r], ew[d], eb[d]);
}

// ---------------- rmsnorm -> g_u ----------------
__global__ void k_rmsnorm(const float* __restrict__ h, const float* __restrict__ w) {
    int r = blockIdx.x, d = threadIdx.x;
    float v = h[r*DM + d];
    float ss = v*v;
    #pragma unroll
    for (int o = 16; o; o >>= 1) ss += __shfl_xor_sync(0xffffffffu, ss, o);
    __shared__ float sh[8];
    int wid = d >> 5, lane = d & 31;
    if (lane == 0) sh[wid] = ss;
    __syncthreads();
    if (wid == 0) {
        float t = (lane < 8) ? sh[lane] : 0.f;
        #pragma unroll
        for (int o = 4; o; o >>= 1) t += __shfl_xor_sync(0xffffffffu, t, o);
        if (lane == 0) sh[0] = t;
    }
    __syncthreads();
    float inv = rsqrtf(sh[0] * (1.0f/DM) + 1e-5f);
    g_u[r*DM + d] = v * inv * w[d];
}

// ---------------- SGEMM: BM=128,BN=64,BK=16,TM=8,TN=4, double-buffered ----------------
template<bool ACC>
__global__ __launch_bounds__(256) void k_gemm(
    const float* __restrict__ A, const float* __restrict__ Wt,
    float* __restrict__ C, int M, int N, int K)
{
    constexpr int BM = 128, BN = 64, BK = 16, TM = 8, TN = 4;
    __shared__ float As[2][BK][BM+4];
    __shared__ float Bs[2][BK][BN+4];

    const int tid = threadIdx.x;
    const int tc = tid % (BN/TN);
    const int tr = tid / (BN/TN);
    const int m0 = blockIdx.y * BM, n0 = blockIdx.x * BN;

    // A loader: 512 float4 per tile -> 2 per thread
    const int am0 = (tid + 0)   / 4, ak0 = ((tid + 0)   % 4) * 4;
    const int am1 = (tid + 256) / 4, ak1 = ((tid + 256) % 4) * 4;
    // B loader: 256 float4 per tile -> 1 per thread
    const int bn = tid / 4, bk = (tid % 4) * 4;

    float acc[TM][TN];
    #pragma unroll
    for (int i = 0; i < TM; i++)
        #pragma unroll
        for (int j = 0; j < TN; j++) acc[i][j] = 0.f;

    const int nk = K / BK;

    // prologue: load tile 0 directly to smem
    {
        float4 va0 = *(const float4*)&A[(size_t)(m0+am0)*K + ak0];
        float4 va1 = *(const float4*)&A[(size_t)(m0+am1)*K + ak1];
        float4 vb  = *(const float4*)&Wt[(size_t)(n0+bn)*K + bk];
        As[0][ak0+0][am0]=va0.x; As[0][ak0+1][am0]=va0.y; As[0][ak0+2][am0]=va0.z; As[0][ak0+3][am0]=va0.w;
        As[0][ak1+0][am1]=va1.x; As[0][ak1+1][am1]=va1.y; As[0][ak1+2][am1]=va1.z; As[0][ak1+3][am1]=va1.w;
        Bs[0][bk+0][bn]=vb.x; Bs[0][bk+1][bn]=vb.y; Bs[0][bk+2][bn]=vb.z; Bs[0][bk+3][bn]=vb.w;
    }
    __syncthreads();

    for (int kb = 0; kb < nk; kb++) {
        const int buf = kb & 1;
        const bool more = (kb + 1 < nk);
        float4 va0, va1, vb;
        if (more) {
            int k0 = (kb+1) * BK;
            va0 = *(const float4*)&A[(size_t)(m0+am0)*K + k0 + ak0];
            va1 = *(const float4*)&A[(size_t)(m0+am1)*K + k0 + ak1];
            vb  = *(const float4*)&Wt[(size_t)(n0+bn)*K + k0 + bk];
        }

        #pragma unroll
        for (int kk = 0; kk < BK; kk++) {
            float a[TM], b[TN];
            float4 a0 = *(const float4*)&As[buf][kk][tr*TM];
            float4 a1 = *(const float4*)&As[buf][kk][tr*TM + 4];
            a[0]=a0.x; a[1]=a0.y; a[2]=a0.z; a[3]=a0.w;
            a[4]=a1.x; a[5]=a1.y; a[6]=a1.z; a[7]=a1.w;
            float4 b0 = *(const float4*)&Bs[buf][kk][tc*TN];
            b[0]=b0.x; b[1]=b0.y; b[2]=b0.z; b[3]=b0.w;
            #pragma unroll
            for (int i = 0; i < TM; i++)
                #pragma unroll
                for (int j = 0; j < TN; j++)
                    acc[i][j] = fmaf(a[i], b[j], acc[i][j]);
        }

        if (more) {
            int nb = buf ^ 1;
            As[nb][ak0+0][am0]=va0.x; As[nb][ak0+1][am0]=va0.y; As[nb][ak0+2][am0]=va0.z; As[nb][ak0+3][am0]=va0.w;
            As[nb][ak1+0][am1]=va1.x; As[nb][ak1+1][am1]=va1.y; As[nb][ak1+2][am1]=va1.z; As[nb][ak1+3][am1]=va1.w;
            Bs[nb][bk+0][bn]=vb.x; Bs[nb][bk+1][bn]=vb.y; Bs[nb][bk+2][bn]=vb.z; Bs[nb][bk+3][bn]=vb.w;
        }
        __syncthreads();
    }

    #pragma unroll
    for (int i = 0; i < TM; i++) {
        size_t rbase = (size_t)(m0 + tr*TM + i)*N + n0 + tc*TN;
        float4* p = (float4*)&C[rbase];
        float4 v = make_float4(acc[i][0], acc[i][1], acc[i][2], acc[i][3]);
        if (ACC) {
            float4 o = *p;
            v.x += o.x; v.y += o.y; v.z += o.z; v.w += o.w;
        }
        *p = v;
    }
}

// ---------------- causal depthwise conv (k=4) + silu (R1 scalar form) ----------------
__global__ void k_conv(const float* __restrict__ cw, const float* __restrict__ cb) {
    int idx = blockIdx.x * blockDim.x + threadIdx.x;
    int e = idx % DI;
    int row = idx / DI;
    int w = row % Wd;
    float acc = cb[e];
    #pragma unroll
    for (int k = 0; k < 4; k++) {
        int ww = w + k - 3;
        if (ww >= 0) acc = fmaf(cw[e*4 + k], g_xz[(size_t)(row + k - 3)*(2*DI) + e], acc);
    }
    g_xs[idx] = acc / (1.f + __expf(-acc));
}

// ---------------- x_proj ----------------
__global__ __launch_bounds__(256) void k_xproj(const float* __restrict__ xpw) {
    __shared__ float sx[8][DI];
    int r0 = blockIdx.x * 8;
    #pragma unroll
    for (int i = 0; i < 4; i++) {
        int idx = threadIdx.x + 256*i;
        int rr = idx / (DI/4);
        int c4 = idx % (DI/4);
        *(float4*)&sx[rr][c4*4] = *(const float4*)&g_xs[(size_t)(r0+rr)*DI + c4*4];
    }
    __syncthreads();
    int warp = threadIdx.x >> 5, lane = threadIdx.x & 31;
    for (int jj = 0; jj < 6; jj++) {
        int j = warp*6 + jj;
        float wreg[16];
        #pragma unroll
        for (int i = 0; i < 16; i++) wreg[i] = xpw[(size_t)j*DI + lane + 32*i];
        #pragma unroll
        for (int rr = 0; rr < 8; rr++) {
            float s = 0.f;
            #pragma unroll
            for (int i = 0; i < 16; i++) s = fmaf(wreg[i], sx[rr][lane + 32*i], s);
            #pragma unroll
            for (int o = 16; o; o >>= 1) s += __shfl_xor_sync(0xffffffffu, s, o);
            if (lane == 0) g_dbc[(size_t)(r0+rr)*48 + j] = s;
        }
    }
}

// ---------------- dt_proj + softplus ----------------
__global__ void k_dt(const float* __restrict__ dtw, const float* __restrict__ dtb) {
    int r = blockIdx.x, d = threadIdx.x;
    __shared__ float sd[DR];
    if (d < DR) sd[d] = g_dbc[(size_t)r*48 + d];
    __syncthreads();
    float acc = dtb[d];
    #pragma unroll
    for (int j = 0; j < DR; j++) acc = fmaf(sd[j], dtw[d*DR + j], acc);
    float e = __expf(-fabsf(acc));
    float sp = fmaxf(acc, 0.f) + __logf(1.f + e);
    g_delta[(size_t)r*DI + d] = sp;
}

// ---------------- selective scan: 8-step register-chunked pipeline, gate fused -------
#define SCAN_LOAD(BUF, CH)                                              \
    {                                                                   \
        size_t tb = (size_t)(CH) * 8;                                   \
        _Pragma("unroll")                                               \
        for (int j = 0; j < 8; j++) {                                   \
            dl##BUF[j] = pd[(tb+j)*DI];                                 \
            ul##BUF[j] = pu[(tb+j)*DI];                                 \
            Bl##BUF[j] = pB[(tb+j)*48];                                 \
            Cl##BUF[j] = pC[(tb+j)*48];                                 \
            zl##BUF[j] = pz[(tb+j)*(2*DI)];                             \
        }                                                               \
    }

#define SCAN_PROC(BUF, CH)                                              \
    {                                                                   \
        size_t tb = (size_t)(CH) * 8;                                   \
        _Pragma("unroll")                                               \
        for (int j = 0; j < 8; j++) {                                   \
            float dc = dl##BUF[j], uc = ul##BUF[j];                     \
            float dA = __expf(dc * Av);                                 \
            hst = fmaf(dA, hst, dc * Bl##BUF[j] * uc);                  \
            float yv = hst * Cl##BUF[j];                                \
            yv += __shfl_xor_sync(0xffffffffu, yv, 8);                  \
            yv += __shfl_xor_sync(0xffffffffu, yv, 4);                  \
            yv += __shfl_xor_sync(0xffffffffu, yv, 2);                  \
            yv += __shfl_xor_sync(0xffffffffu, yv, 1);                  \
            if (s == 0) {                                               \
                float zc = zl##BUF[j];                                  \
                float g = zc / (1.f + __expf(-zc));                     \
                py[(tb+j)*DI] = fmaf(uc, Dpv, yv) * g;                  \
            }                                                           \
        }                                                               \
    }

__global__ __launch_bounds__(128) void k_scan(const float* __restrict__ A_log,
                                              const float* __restrict__ Dp) {
    int gw = (blockIdx.x * blockDim.x + threadIdx.x) >> 5;
    int lane = threadIdx.x & 31;
    int b = gw >> 8;
    int dpair = gw & 255;
    int s = lane & 15;
    int dd = dpair*2 + (lane >> 4);

    float Av = -expf(A_log[dd*DS + s]);
    float Dpv = Dp[dd];
    float hst = 0.f;

    const float* pd = g_delta + (size_t)b*Wd*DI + dd;
    const float* pu = g_xs    + (size_t)b*Wd*DI + dd;
    const float* pB = g_dbc   + (size_t)b*Wd*48 + DR + s;
    const float* pC = g_dbc   + (size_t)b*Wd*48 + DR + DS + s;
    const float* pz = g_xz    + (size_t)b*Wd*(2*DI) + DI + dd;
    float* py = g_y + (size_t)b*Wd*DI + dd;

    float dl0[8], ul0[8], Bl0[8], Cl0[8], zl0[8];
    float dl1[8], ul1[8], Bl1[8], Cl1[8], zl1[8];

    constexpr int NCH = Wd / 8;       // 256 chunks

    SCAN_LOAD(0, 0)
    #pragma unroll 1
    for (int c = 0; c < NCH; c += 2) {
        if (c + 1 < NCH) SCAN_LOAD(1, c+1)
        SCAN_PROC(0, c)
        if (c + 2 < NCH) SCAN_LOAD(0, c+2)
        if (c + 1 < NCH) SCAN_PROC(1, c+1)
    }
}

// ---------------- host launch ----------------
extern "C" void kernel_launch(void* const* d_in, const int* in_sizes, int n_in,
                              void* d_out, int out_size) {
    const float* x         = (const float*)d_in[0];
    const float* emb_w     = (const float*)d_in[1];
    const float* emb_b     = (const float*)d_in[2];
    const float* in_proj_w = (const float*)d_in[3];
    const float* conv_w    = (const float*)d_in[4];
    const float* conv_b    = (const float*)d_in[5];
    const float* x_proj_w  = (const float*)d_in[6];
    const float* dt_proj_w = (const float*)d_in[7];
    const float* dt_proj_b = (const float*)d_in[8];
    const float* A_log     = (const float*)d_in[9];
    const float* Dp        = (const float*)d_in[10];
    const float* out_proj_w= (const float*)d_in[11];
    const float* norm_w    = (const float*)d_in[12];
    float* h = (float*)d_out;

    float *p_u, *p_xz, *p_y;
    cudaGetSymbolAddress((void**)&p_u,  g_u);
    cudaGetSymbolAddress((void**)&p_xz, g_xz);
    cudaGetSymbolAddress((void**)&p_y,  g_y);

    k_embed<<<NROW, DM>>>(x, emb_w, emb_b, h);

    for (int l = 0; l < 2; ++l) {
        const float* inw = in_proj_w + (size_t)l * (2*DI) * DM;
        const float* cw  = conv_w   + (size_t)l * DI * 4;
        const float* cb  = conv_b   + (size_t)l * DI;
        const float* xpw = x_proj_w + (size_t)l * 48 * DI;
        const float* dtw = dt_proj_w+ (size_t)l * DI * DR;
        const float* dtb = dt_proj_b+ (size_t)l * DI;
        const float* al  = A_log    + (size_t)l * DI * DS;
        const float* dp  = Dp       + (size_t)l * DI;
        const float* ow  = out_proj_w + (size_t)l * DM * DI;
        const float* nw  = norm_w   + (size_t)l * DM;

        k_rmsnorm<<<NROW, DM>>>(h, nw);

        // xz = u @ in_w^T : M=8192, N=1024, K=256
        {
            dim3 grid((2*DI)/64, NROW/128);
            k_gemm<false><<<grid, 256>>>(p_u, inw, p_xz, NROW, 2*DI, DM);
        }

        k_conv<<<(NROW*DI)/256, 256>>>(cw, cb);
        k_xproj<<<NROW/8, 256>>>(xpw);
        k_dt<<<NROW, DI>>>(dtw, dtb);
        k_scan<<<(Bq*(DI/2)*32)/128, 128>>>(al, dp);

        // h += y @ ow^T : M=8192, N=256, K=512
        {
            dim3 grid(DM/64, NROW/128);
            k_gemm<true><<<grid, 256>>>(p_y, ow, h, NROW, DM, DI);
        }
    }
}

// round 5
// speedup vs baseline: 1.8936x; 1.1288x over previous
#include <cuda_runtime.h>
#include <math.h>

#define Bq 4
#define Wd 2048
#define DM 256
#define DI 512
#define DS 16
#define DR 16
#define NROW (Bq*Wd)   // 8192

// ---------------- static scratch ----------------
__device__ float g_u[NROW*DM];
__device__ float g_xz[NROW*2*DI];
__device__ float g_xs[NROW*DI];
__device__ float g_dbc[NROW*48];
__device__ float g_delta[NROW*DI];
__device__ float g_y[NROW*DI];

// ---------------- embed ----------------
__global__ void k_embed(const float* __restrict__ x, const float* __restrict__ ew,
                        const float* __restrict__ eb, float* __restrict__ h) {
    int r = blockIdx.x, d = threadIdx.x;
    h[r*DM + d] = fmaf(x[r], ew[d], eb[d]);
}

// ---------------- rmsnorm -> g_u ----------------
__global__ void k_rmsnorm(const float* __restrict__ h, const float* __restrict__ w) {
    int r = blockIdx.x, d = threadIdx.x;
    float v = h[r*DM + d];
    float ss = v*v;
    #pragma unroll
    for (int o = 16; o; o >>= 1) ss += __shfl_xor_sync(0xffffffffu, ss, o);
    __shared__ float sh[8];
    int wid = d >> 5, lane = d & 31;
    if (lane == 0) sh[wid] = ss;
    __syncthreads();
    if (wid == 0) {
        float t = (lane < 8) ? sh[lane] : 0.f;
        #pragma unroll
        for (int o = 4; o; o >>= 1) t += __shfl_xor_sync(0xffffffffu, t, o);
        if (lane == 0) sh[0] = t;
    }
    __syncthreads();
    float inv = rsqrtf(sh[0] * (1.0f/DM) + 1e-5f);
    g_u[r*DM + d] = v * inv * w[d];
}

// ---------------- SGEMM: BM=128, BK=16, TM=8; BN/TN templated; double-buffered -------
template<int BN, int TN, bool ACC>
__global__ __launch_bounds__(256) void k_gemm(
    const float* __restrict__ A, const float* __restrict__ Wt,
    float* __restrict__ C, int M, int N, int K)
{
    constexpr int BM = 128, BK = 16, TM = 8;
    constexpr int ANUM = (BM*BK)/(256*4);   // 2
    constexpr int BNUM = (BN*BK)/(256*4);   // 2 (BN=128) or 1 (BN=64)
    __shared__ float As[2][BK][BM+4];
    __shared__ float Bs[2][BK][BN+4];

    const int tid = threadIdx.x;
    const int tc = tid % (BN/TN);
    const int tr = tid / (BN/TN);
    const int m0 = blockIdx.y * BM, n0 = blockIdx.x * BN;

    int am[ANUM], ak[ANUM], bn[BNUM], bk[BNUM];
    #pragma unroll
    for (int i = 0; i < ANUM; i++) {
        int idx = tid + 256*i;
        am[i] = idx >> 2; ak[i] = (idx & 3) * 4;
    }
    #pragma unroll
    for (int i = 0; i < BNUM; i++) {
        int idx = tid + 256*i;
        bn[i] = idx >> 2; bk[i] = (idx & 3) * 4;
    }

    float acc[TM][TN];
    #pragma unroll
    for (int i = 0; i < TM; i++)
        #pragma unroll
        for (int j = 0; j < TN; j++) acc[i][j] = 0.f;

    const int nk = K / BK;

    // prologue
    #pragma unroll
    for (int i = 0; i < ANUM; i++) {
        float4 v = *(const float4*)&A[(size_t)(m0+am[i])*K + ak[i]];
        As[0][ak[i]+0][am[i]]=v.x; As[0][ak[i]+1][am[i]]=v.y;
        As[0][ak[i]+2][am[i]]=v.z; As[0][ak[i]+3][am[i]]=v.w;
    }
    #pragma unroll
    for (int i = 0; i < BNUM; i++) {
        float4 v = *(const float4*)&Wt[(size_t)(n0+bn[i])*K + bk[i]];
        Bs[0][bk[i]+0][bn[i]]=v.x; Bs[0][bk[i]+1][bn[i]]=v.y;
        Bs[0][bk[i]+2][bn[i]]=v.z; Bs[0][bk[i]+3][bn[i]]=v.w;
    }
    __syncthreads();

    for (int kb = 0; kb < nk; kb++) {
        const int buf = kb & 1;
        const bool more = (kb + 1 < nk);
        float4 va[ANUM], vb[BNUM];
        if (more) {
            int k0 = (kb+1) * BK;
            #pragma unroll
            for (int i = 0; i < ANUM; i++)
                va[i] = *(const float4*)&A[(size_t)(m0+am[i])*K + k0 + ak[i]];
            #pragma unroll
            for (int i = 0; i < BNUM; i++)
                vb[i] = *(const float4*)&Wt[(size_t)(n0+bn[i])*K + k0 + bk[i]];
        }

        #pragma unroll
        for (int kk = 0; kk < BK; kk++) {
            float a[TM], b[TN];
            float4 a0 = *(const float4*)&As[buf][kk][tr*TM];
            float4 a1 = *(const float4*)&As[buf][kk][tr*TM + 4];
            a[0]=a0.x; a[1]=a0.y; a[2]=a0.z; a[3]=a0.w;
            a[4]=a1.x; a[5]=a1.y; a[6]=a1.z; a[7]=a1.w;
            float4 b0 = *(const float4*)&Bs[buf][kk][tc*TN];
            b[0]=b0.x; b[1]=b0.y; b[2]=b0.z; b[3]=b0.w;
            if (TN == 8) {
                float4 b1 = *(const float4*)&Bs[buf][kk][tc*TN + 4];
                b[4]=b1.x; b[5]=b1.y; b[6]=b1.z; b[7]=b1.w;
            }
            #pragma unroll
            for (int i = 0; i < TM; i++)
                #pragma unroll
                for (int j = 0; j < TN; j++)
                    acc[i][j] = fmaf(a[i], b[j], acc[i][j]);
        }

        if (more) {
            int nb = buf ^ 1;
            #pragma unroll
            for (int i = 0; i < ANUM; i++) {
                As[nb][ak[i]+0][am[i]]=va[i].x; As[nb][ak[i]+1][am[i]]=va[i].y;
                As[nb][ak[i]+2][am[i]]=va[i].z; As[nb][ak[i]+3][am[i]]=va[i].w;
            }
            #pragma unroll
            for (int i = 0; i < BNUM; i++) {
                Bs[nb][bk[i]+0][bn[i]]=vb[i].x; Bs[nb][bk[i]+1][bn[i]]=vb[i].y;
                Bs[nb][bk[i]+2][bn[i]]=vb[i].z; Bs[nb][bk[i]+3][bn[i]]=vb[i].w;
            }
        }
        __syncthreads();
    }

    #pragma unroll
    for (int i = 0; i < TM; i++) {
        size_t rbase = (size_t)(m0 + tr*TM + i)*N + n0 + tc*TN;
        #pragma unroll
        for (int j4 = 0; j4 < TN/4; j4++) {
            float4* p = (float4*)&C[rbase + 4*j4];
            float4 v = make_float4(acc[i][4*j4+0], acc[i][4*j4+1],
                                   acc[i][4*j4+2], acc[i][4*j4+3]);
            if (ACC) {
                float4 o = *p;
                v.x += o.x; v.y += o.y; v.z += o.z; v.w += o.w;
            }
            *p = v;
        }
    }
}

// ---------------- causal depthwise conv (k=4) + silu ----------------
__global__ void k_conv(const float* __restrict__ cw, const float* __restrict__ cb) {
    int idx = blockIdx.x * blockDim.x + threadIdx.x;
    int e = idx % DI;
    int row = idx / DI;
    int w = row % Wd;
    float acc = cb[e];
    #pragma unroll
    for (int k = 0; k < 4; k++) {
        int ww = w + k - 3;
        if (ww >= 0) acc = fmaf(cw[e*4 + k], g_xz[(size_t)(row + k - 3)*(2*DI) + e], acc);
    }
    g_xs[idx] = acc / (1.f + __expf(-acc));
}

// ---------------- x_proj + dt_proj + softplus (fused) ----------------
__global__ __launch_bounds__(256) void k_xproj(const float* __restrict__ xpw,
                                               const float* __restrict__ dtw,
                                               const float* __restrict__ dtb) {
    __shared__ float sx[8][DI];      // 16 KB
    __shared__ float sdt[8][DR];     // dt_rank part of dbc
    int r0 = blockIdx.x * 8;
    #pragma unroll
    for (int i = 0; i < 4; i++) {
        int idx = threadIdx.x + 256*i;
        int rr = idx / (DI/4);
        int c4 = idx % (DI/4);
        *(float4*)&sx[rr][c4*4] = *(const float4*)&g_xs[(size_t)(r0+rr)*DI + c4*4];
    }
    __syncthreads();
    int warp = threadIdx.x >> 5, lane = threadIdx.x & 31;
    for (int jj = 0; jj < 6; jj++) {
        int j = warp*6 + jj;
        float wreg[16];
        #pragma unroll
        for (int i = 0; i < 16; i++) wreg[i] = xpw[(size_t)j*DI + lane + 32*i];
        #pragma unroll
        for (int rr = 0; rr < 8; rr++) {
            float s = 0.f;
            #pragma unroll
            for (int i = 0; i < 16; i++) s = fmaf(wreg[i], sx[rr][lane + 32*i], s);
            #pragma unroll
            for (int o = 16; o; o >>= 1) s += __shfl_xor_sync(0xffffffffu, s, o);
            if (lane == 0) {
                if (j < DR) sdt[rr][j] = s;                  // dt stays in smem
                else        g_dbc[(size_t)(r0+rr)*48 + j] = s;  // B/C for scan
            }
        }
    }
    __syncthreads();
    // dt_proj + softplus: 8 rows x 512 d = 4096 outputs, 16 per thread
    #pragma unroll
    for (int it = 0; it < 16; it++) {
        int o = threadIdx.x + 256*it;
        int rr = o >> 9;
        int d = o & (DI-1);
        float acc = dtb[d];
        #pragma unroll
        for (int j = 0; j < DR; j++) acc = fmaf(sdt[rr][j], dtw[d*DR + j], acc);
        float e = __expf(-fabsf(acc));
        float sp = fmaxf(acc, 0.f) + __logf(1.f + e);
        g_delta[(size_t)(r0+rr)*DI + d] = sp;
    }
}

// ---------------- selective scan: 8-step register-chunked pipeline, gate fused -------
#define SCAN_LOAD(BUF, CH)                                              \
    {                                                                   \
        size_t tb = (size_t)(CH) * 8;                                   \
        _Pragma("unroll")                                               \
        for (int j = 0; j < 8; j++) {                                   \
            dl##BUF[j] = pd[(tb+j)*DI];                                 \
            ul##BUF[j] = pu[(tb+j)*DI];                                 \
            Bl##BUF[j] = pB[(tb+j)*48];                                 \
            Cl##BUF[j] = pC[(tb+j)*48];                                 \
            zl##BUF[j] = pz[(tb+j)*(2*DI)];                             \
        }                                                               \
    }

#define SCAN_PROC(BUF, CH)                                              \
    {                                                                   \
        size_t tb = (size_t)(CH) * 8;                                   \
        _Pragma("unroll")                                               \
        for (int j = 0; j < 8; j++) {                                   \
            float dc = dl##BUF[j], uc = ul##BUF[j];                     \
            float dA = __expf(dc * Av);                                 \
            hst = fmaf(dA, hst, dc * Bl##BUF[j] * uc);                  \
            float yv = hst * Cl##BUF[j];                                \
            yv += __shfl_xor_sync(0xffffffffu, yv, 8);                  \
            yv += __shfl_xor_sync(0xffffffffu, yv, 4);                  \
            yv += __shfl_xor_sync(0xffffffffu, yv, 2);                  \
            yv += __shfl_xor_sync(0xffffffffu, yv, 1);                  \
            if (s == 0) {                                               \
                float zc = zl##BUF[j];                                  \
                float g = zc / (1.f + __expf(-zc));                     \
                py[(tb+j)*DI] = fmaf(uc, Dpv, yv) * g;                  \
            }                                                           \
        }                                                               \
    }

__global__ __launch_bounds__(128) void k_scan(const float* __restrict__ A_log,
                                              const float* __restrict__ Dp) {
    int gw = (blockIdx.x * blockDim.x + threadIdx.x) >> 5;
    int lane = threadIdx.x & 31;
    int b = gw >> 8;
    int dpair = gw & 255;
    int s = lane & 15;
    int dd = dpair*2 + (lane >> 4);

    float Av = -expf(A_log[dd*DS + s]);
    float Dpv = Dp[dd];
    float hst = 0.f;

    const float* pd = g_delta + (size_t)b*Wd*DI + dd;
    const float* pu = g_xs    + (size_t)b*Wd*DI + dd;
    const float* pB = g_dbc   + (size_t)b*Wd*48 + DR + s;
    const float* pC = g_dbc   + (size_t)b*Wd*48 + DR + DS + s;
    const float* pz = g_xz    + (size_t)b*Wd*(2*DI) + DI + dd;
    float* py = g_y + (size_t)b*Wd*DI + dd;

    float dl0[8], ul0[8], Bl0[8], Cl0[8], zl0[8];
    float dl1[8], ul1[8], Bl1[8], Cl1[8], zl1[8];

    constexpr int NCH = Wd / 8;       // 256 chunks

    SCAN_LOAD(0, 0)
    #pragma unroll 1
    for (int c = 0; c < NCH; c += 2) {
        if (c + 1 < NCH) SCAN_LOAD(1, c+1)
        SCAN_PROC(0, c)
        if (c + 2 < NCH) SCAN_LOAD(0, c+2)
        if (c + 1 < NCH) SCAN_PROC(1, c+1)
    }
}

// ---------------- host launch ----------------
extern "C" void kernel_launch(void* const* d_in, const int* in_sizes, int n_in,
                              void* d_out, int out_size) {
    const float* x         = (const float*)d_in[0];
    const float* emb_w     = (const float*)d_in[1];
    const float* emb_b     = (const float*)d_in[2];
    const float* in_proj_w = (const float*)d_in[3];
    const float* conv_w    = (const float*)d_in[4];
    const float* conv_b    = (const float*)d_in[5];
    const float* x_proj_w  = (const float*)d_in[6];
    const float* dt_proj_w = (const float*)d_in[7];
    const float* dt_proj_b = (const float*)d_in[8];
    const float* A_log     = (const float*)d_in[9];
    const float* Dp        = (const float*)d_in[10];
    const float* out_proj_w= (const float*)d_in[11];
    const float* norm_w    = (const float*)d_in[12];
    float* h = (float*)d_out;

    float *p_u, *p_xz, *p_y;
    cudaGetSymbolAddress((void**)&p_u,  g_u);
    cudaGetSymbolAddress((void**)&p_xz, g_xz);
    cudaGetSymbolAddress((void**)&p_y,  g_y);

    k_embed<<<NROW, DM>>>(x, emb_w, emb_b, h);

    for (int l = 0; l < 2; ++l) {
        const float* inw = in_proj_w + (size_t)l * (2*DI) * DM;
        const float* cw  = conv_w   + (size_t)l * DI * 4;
        const float* cb  = conv_b   + (size_t)l * DI;
        const float* xpw = x_proj_w + (size_t)l * 48 * DI;
        const float* dtw = dt_proj_w+ (size_t)l * DI * DR;
        const float* dtb = dt_proj_b+ (size_t)l * DI;
        const float* al  = A_log    + (size_t)l * DI * DS;
        const float* dp  = Dp       + (size_t)l * DI;
        const float* ow  = out_proj_w + (size_t)l * DM * DI;
        const float* nw  = norm_w   + (size_t)l * DM;

        k_rmsnorm<<<NROW, DM>>>(h, nw);

        // xz = u @ in_w^T : M=8192, N=1024, K=256  (BN=128, TN=8)
        {
            dim3 grid((2*DI)/128, NROW/128);
            k_gemm<128,8,false><<<grid, 256>>>(p_u, inw, p_xz, NROW, 2*DI, DM);
        }

        k_conv<<<(NROW*DI)/256, 256>>>(cw, cb);
        k_xproj<<<NROW/8, 256>>>(xpw, dtw, dtb);
        k_scan<<<(Bq*(DI/2)*32)/128, 128>>>(al, dp);

        // h += y @ ow^T : M=8192, N=256, K=512  (BN=64, TN=4)
        {
            dim3 grid(DM/64, NROW/128);
            k_gemm<64,4,true><<<grid, 256>>>(p_y, ow, h, NROW, DM, DI);
        }
    }
}

// round 8
// speedup vs baseline: 2.0670x; 1.0916x over previous
#include <cuda_runtime.h>
#include <cuda_bf16.h>
#include <cstdint>
#include <math.h>

#define Bq 4
#define Wd 2048
#define DM 256
#define DI 512
#define DS 16
#define DR 16
#define NROW (Bq*Wd)   // 8192

// ---------------- static scratch ----------------
__device__ float g_u[NROW*DM];
__device__ float g_xz[NROW*2*DI];
__device__ float g_xs[NROW*DI];
__device__ float g_dbc[NROW*48];
__device__ float g_delta[NROW*DI];
__device__ float g_y[NROW*DI];
__device__ __nv_bfloat16 g_act3[(size_t)NROW*1536];   // split activations (3K max 1536)
__device__ __nv_bfloat16 g_w3[(size_t)1024*1536];     // split weights

__device__ __forceinline__ uint32_t smem_u32(const void* p) {
    uint32_t a;
    asm("{ .reg .u64 t; cvta.to.shared.u64 t, %1; cvt.u32.u64 %0, t; }"
        : "=r"(a) : "l"(p));
    return a;
}
__device__ __forceinline__ void ldsm4(uint32_t& r0, uint32_t& r1, uint32_t& r2,
                                      uint32_t& r3, uint32_t addr) {
    asm volatile("ldmatrix.sync.aligned.m8n8.x4.shared.b16 {%0,%1,%2,%3}, [%4];"
                 : "=r"(r0), "=r"(r1), "=r"(r2), "=r"(r3) : "r"(addr));
}
__device__ __forceinline__ void mma_bf16(float* d, const uint32_t* a, const uint32_t* b) {
    asm volatile("mma.sync.aligned.m16n8k16.row.col.f32.bf16.bf16.f32 "
                 "{%0,%1,%2,%3}, {%4,%5,%6,%7}, {%8,%9}, {%0,%1,%2,%3};"
                 : "+f"(d[0]), "+f"(d[1]), "+f"(d[2]), "+f"(d[3])
                 : "r"(a[0]), "r"(a[1]), "r"(a[2]), "r"(a[3]), "r"(b[0]), "r"(b[1]));
}

// ---------------- embed ----------------
__global__ void k_embed(const float* __restrict__ x, const float* __restrict__ ew,
                        const float* __restrict__ eb, float* __restrict__ h) {
    int r = blockIdx.x, d = threadIdx.x;
    h[r*DM + d] = fmaf(x[r], ew[d], eb[d]);
}

// ---------------- rmsnorm -> g_u ----------------
__global__ void k_rmsnorm(const float* __restrict__ h, const float* __restrict__ w) {
    int r = blockIdx.x, d = threadIdx.x;
    float v = h[r*DM + d];
    float ss = v*v;
    #pragma unroll
    for (int o = 16; o; o >>= 1) ss += __shfl_xor_sync(0xffffffffu, ss, o);
    __shared__ float sh[8];
    int wid = d >> 5, lane = d & 31;
    if (lane == 0) sh[wid] = ss;
    __syncthreads();
    if (wid == 0) {
        float t = (lane < 8) ? sh[lane] : 0.f;
        #pragma unroll
        for (int o = 4; o; o >>= 1) t += __shfl_xor_sync(0xffffffffu, t, o);
        if (lane == 0) sh[0] = t;
    }
    __syncthreads();
    float inv = rsqrtf(sh[0] * (1.0f/DM) + 1e-5f);
    g_u[r*DM + d] = v * inv * w[d];
}

// ---------------- split fp32 -> bf16 concatenation ----------------
// act (s1lo=0): [hi, hi, lo]; weights (s1lo=1): [hi, lo, hi]
// sum over 3K: hi*hi + hi*lo + lo*hi  (drops lo*lo ~ 2^-32)
__global__ void k_cvt(const float* __restrict__ src, __nv_bfloat16* __restrict__ dst,
                      int K, int s1lo) {
    int idx = blockIdx.x * blockDim.x + threadIdx.x;
    int r = idx / K, k = idx % K;
    float x = src[idx];
    __nv_bfloat16 hi = __float2bfloat16(x);
    __nv_bfloat16 lo = __float2bfloat16(x - __bfloat162float(hi));
    size_t b = (size_t)r * 3 * K;
    dst[b + k] = hi;
    dst[b + K + k]   = s1lo ? lo : hi;
    dst[b + 2*K + k] = s1lo ? hi : lo;
}

// ---------------- mma.sync bf16 GEMM: C[m,n] (+)= sum_k A3[m,k]*B3[n,k] -------------
// BM=128, BK=32 bf16. 8 warps: 4(m) x 2(n). Warp tile 32 x (BN/2).
template<int BN, bool ACC>
__global__ __launch_bounds__(256) void k_mgemm(
    const __nv_bfloat16* __restrict__ A3, const __nv_bfloat16* __restrict__ B3,
    float* __restrict__ C, int N, int K3)
{
    constexpr int BM = 128, BK = 32;
    constexpr int LD = 40;                    // padded row stride (bf16): 80B
    constexpr int NI = BN / 16;               // n8-tiles per warp: 8 or 4
    constexpr int AV = (BM*BK)/(8*256);       // uint4/thread for A: 2
    constexpr int BV = (BN*BK)/(8*256);       // 2 (BN=128) or 1 (BN=64)
    __shared__ __nv_bfloat16 smA[2][BM*LD];
    __shared__ __nv_bfloat16 smB[2][BN*LD];

    const int tid = threadIdx.x;
    const int wid = tid >> 5, lane = tid & 31;
    const int wm = (wid & 3) * 32;            // warp m offset
    const int wn = (wid >> 2) * (BN/2);       // warp n offset
    const int m0 = blockIdx.y * BM, n0 = blockIdx.x * BN;
    const int nch = K3 / BK;

    float acc[2][NI][4];
    #pragma unroll
    for (int mi = 0; mi < 2; mi++)
        #pragma unroll
        for (int ni = 0; ni < NI; ni++)
            #pragma unroll
            for (int j = 0; j < 4; j++) acc[mi][ni][j] = 0.f;

    // loader coords (4 uint4 per 32-bf16 row)
    int arow[AV], aq[AV], brow[BV], bq[BV];
    #pragma unroll
    for (int i = 0; i < AV; i++) { int idx = tid + 256*i; arow[i] = idx >> 2; aq[i] = idx & 3; }
    #pragma unroll
    for (int i = 0; i < BV; i++) { int idx = tid + 256*i; brow[i] = idx >> 2; bq[i] = idx & 3; }

    // prologue: chunk 0 -> smem
    #pragma unroll
    for (int i = 0; i < AV; i++)
        *(uint4*)&smA[0][arow[i]*LD + aq[i]*8] =
            *(const uint4*)(A3 + (size_t)(m0+arow[i])*K3 + aq[i]*8);
    #pragma unroll
    for (int i = 0; i < BV; i++)
        *(uint4*)&smB[0][brow[i]*LD + bq[i]*8] =
            *(const uint4*)(B3 + (size_t)(n0+brow[i])*K3 + bq[i]*8);
    __syncthreads();

    for (int c = 0; c < nch; c++) {
        const int buf = c & 1;
        const bool more = (c + 1 < nch);
        uint4 va[AV], vb[BV];
        if (more) {
            int k0 = (c+1) * BK;
            #pragma unroll
            for (int i = 0; i < AV; i++)
                va[i] = *(const uint4*)(A3 + (size_t)(m0+arow[i])*K3 + k0 + aq[i]*8);
            #pragma unroll
            for (int i = 0; i < BV; i++)
                vb[i] = *(const uint4*)(B3 + (size_t)(n0+brow[i])*K3 + k0 + bq[i]*8);
        }

        #pragma unroll
        for (int k16 = 0; k16 < 2; k16++) {
            const int k0 = k16 * 16;
            uint32_t a[2][4];
            #pragma unroll
            for (int mi = 0; mi < 2; mi++) {
                uint32_t addr = smem_u32(
                    &smA[buf][(wm + mi*16 + (lane & 15))*LD + k0 + (lane >> 4)*8]);
                ldsm4(a[mi][0], a[mi][1], a[mi][2], a[mi][3], addr);
            }
            uint32_t b[NI][2];
            #pragma unroll
            for (int ng = 0; ng < NI/2; ng++) {
                uint32_t r0, r1, r2, r3;
                uint32_t addr = smem_u32(
                    &smB[buf][(wn + ng*16 + (lane & 15))*LD + k0 + (lane >> 4)*8]);
                ldsm4(r0, r1, r2, r3, addr);
                b[2*ng][0] = r0; b[2*ng][1] = r2;
                b[2*ng+1][0] = r1; b[2*ng+1][1] = r3;
            }
            #pragma unroll
            for (int mi = 0; mi < 2; mi++)
                #pragma unroll
                for (int ni = 0; ni < NI; ni++)
                    mma_bf16(acc[mi][ni], a[mi], b[ni]);
        }

        if (more) {
            int nb = buf ^ 1;
            #pragma unroll
            for (int i = 0; i < AV; i++)
                *(uint4*)&smA[nb][arow[i]*LD + aq[i]*8] = va[i];
            #pragma unroll
            for (int i = 0; i < BV; i++)
                *(uint4*)&smB[nb][brow[i]*LD + bq[i]*8] = vb[i];
        }
        __syncthreads();
    }

    // epilogue: fragment layout m16n8: row = lane/4 (+8), col = (lane%4)*2 (+1)
    #pragma unroll
    for (int mi = 0; mi < 2; mi++) {
        #pragma unroll
        for (int ni = 0; ni < NI; ni++) {
            int m = m0 + wm + mi*16 + (lane >> 2);
            int n = n0 + wn + ni*8 + (lane & 3)*2;
            float2* p0 = (float2*)&C[(size_t)m*N + n];
            float2* p1 = (float2*)&C[(size_t)(m+8)*N + n];
            float2 v0 = make_float2(acc[mi][ni][0], acc[mi][ni][1]);
            float2 v1 = make_float2(acc[mi][ni][2], acc[mi][ni][3]);
            if (ACC) {
                float2 o0 = *p0, o1 = *p1;
                v0.x += o0.x; v0.y += o0.y; v1.x += o1.x; v1.y += o1.y;
            }
            *p0 = v0; *p1 = v1;
        }
    }
}

// ---------------- causal depthwise conv (k=4) + silu ----------------
__global__ void k_conv(const float* __restrict__ cw, const float* __restrict__ cb) {
    int idx = blockIdx.x * blockDim.x + threadIdx.x;
    int e = idx % DI;
    int row = idx / DI;
    int w = row % Wd;
    float acc = cb[e];
    #pragma unroll
    for (int k = 0; k < 4; k++) {
        int ww = w + k - 3;
        if (ww >= 0) acc = fmaf(cw[e*4 + k], g_xz[(size_t)(row + k - 3)*(2*DI) + e], acc);
    }
    g_xs[idx] = acc / (1.f + __expf(-acc));
}

// ---------------- x_proj + dt_proj + softplus (fused) ----------------
__global__ __launch_bounds__(256) void k_xproj(const float* __restrict__ xpw,
                                               const float* __restrict__ dtw,
                                               const float* __restrict__ dtb) {
    __shared__ float sx[8][DI];
    __shared__ float sdt[8][DR];
    int r0 = blockIdx.x * 8;
    #pragma unroll
    for (int i = 0; i < 4; i++) {
        int idx = threadIdx.x + 256*i;
        int rr = idx / (DI/4);
        int c4 = idx % (DI/4);
        *(float4*)&sx[rr][c4*4] = *(const float4*)&g_xs[(size_t)(r0+rr)*DI + c4*4];
    }
    __syncthreads();
    int warp = threadIdx.x >> 5, lane = threadIdx.x & 31;
    for (int jj = 0; jj < 6; jj++) {
        int j = warp*6 + jj;
        float wreg[16];
        #pragma unroll
        for (int i = 0; i < 16; i++) wreg[i] = xpw[(size_t)j*DI + lane + 32*i];
        #pragma unroll
        for (int rr = 0; rr < 8; rr++) {
            float s = 0.f;
            #pragma unroll
            for (int i = 0; i < 16; i++) s = fmaf(wreg[i], sx[rr][lane + 32*i], s);
            #pragma unroll
            for (int o = 16; o; o >>= 1) s += __shfl_xor_sync(0xffffffffu, s, o);
            if (lane == 0) {
                if (j < DR) sdt[rr][j] = s;
                else        g_dbc[(size_t)(r0+rr)*48 + j] = s;
            }
        }
    }
    __syncthreads();
    #pragma unroll
    for (int it = 0; it < 16; it++) {
        int o = threadIdx.x + 256*it;
        int rr = o >> 9;
        int d = o & (DI-1);
        float acc = dtb[d];
        #pragma unroll
        for (int j = 0; j < DR; j++) acc = fmaf(sdt[rr][j], dtw[d*DR + j], acc);
        float e = __expf(-fabsf(acc));
        float sp = fmaxf(acc, 0.f) + __logf(1.f + e);
        g_delta[(size_t)(r0+rr)*DI + d] = sp;
    }
}

// ---------------- selective scan: 8-step register-chunked pipeline, gate fused -------
#define SCAN_LOAD(BUF, CH)                                              \
    {                                                                   \
        size_t tb = (size_t)(CH) * 8;                                   \
        _Pragma("unroll")                                               \
        for (int j = 0; j < 8; j++) {                                   \
            dl##BUF[j] = pd[(tb+j)*DI];                                 \
            ul##BUF[j] = pu[(tb+j)*DI];                                 \
            Bl##BUF[j] = pB[(tb+j)*48];                                 \
            Cl##BUF[j] = pC[(tb+j)*48];                                 \
            zl##BUF[j] = pz[(tb+j)*(2*DI)];                             \
        }                                                               \
    }

#define SCAN_PROC(BUF, CH)                                              \
    {                                                                   \
        size_t tb = (size_t)(CH) * 8;                                   \
        _Pragma("unroll")                                               \
        for (int j = 0; j < 8; j++) {                                   \
            float dc = dl##BUF[j], uc = ul##BUF[j];                     \
            float dA = __expf(dc * Av);                                 \
            hst = fmaf(dA, hst, dc * Bl##BUF[j] * uc);                  \
            float yv = hst * Cl##BUF[j];                                \
            yv += __shfl_xor_sync(0xffffffffu, yv, 8);                  \
            yv += __shfl_xor_sync(0xffffffffu, yv, 4);                  \
            yv += __shfl_xor_sync(0xffffffffu, yv, 2);                  \
            yv += __shfl_xor_sync(0xffffffffu, yv, 1);                  \
            if (s == 0) {                                               \
                float zc = zl##BUF[j];                                  \
                float g = zc / (1.f + __expf(-zc));                     \
                py[(tb+j)*DI] = fmaf(uc, Dpv, yv) * g;                  \
            }                                                           \
        }                                                               \
    }

__global__ __launch_bounds__(128) void k_scan(const float* __restrict__ A_log,
                                              const float* __restrict__ Dp) {
    int gw = (blockIdx.x * blockDim.x + threadIdx.x) >> 5;
    int lane = threadIdx.x & 31;
    int b = gw >> 8;
    int dpair = gw & 255;
    int s = lane & 15;
    int dd = dpair*2 + (lane >> 4);

    float Av = -expf(A_log[dd*DS + s]);
    float Dpv = Dp[dd];
    float hst = 0.f;

    const float* pd = g_delta + (size_t)b*Wd*DI + dd;
    const float* pu = g_xs    + (size_t)b*Wd*DI + dd;
    const float* pB = g_dbc   + (size_t)b*Wd*48 + DR + s;
    const float* pC = g_dbc   + (size_t)b*Wd*48 + DR + DS + s;
    const float* pz = g_xz    + (size_t)b*Wd*(2*DI) + DI + dd;
    float* py = g_y + (size_t)b*Wd*DI + dd;

    float dl0[8], ul0[8], Bl0[8], Cl0[8], zl0[8];
    float dl1[8], ul1[8], Bl1[8], Cl1[8], zl1[8];

    constexpr int NCH = Wd / 8;

    SCAN_LOAD(0, 0)
    #pragma unroll 1
    for (int c = 0; c < NCH; c += 2) {
        if (c + 1 < NCH) SCAN_LOAD(1, c+1)
        SCAN_PROC(0, c)
        if (c + 2 < NCH) SCAN_LOAD(0, c+2)
        if (c + 1 < NCH) SCAN_PROC(1, c+1)
    }
}

// ---------------- host launch ----------------
extern "C" void kernel_launch(void* const* d_in, const int* in_sizes, int n_in,
                              void* d_out, int out_size) {
    const float* x         = (const float*)d_in[0];
    const float* emb_w     = (const float*)d_in[1];
    const float* emb_b     = (const float*)d_in[2];
    const float* in_proj_w = (const float*)d_in[3];
    const float* conv_w    = (const float*)d_in[4];
    const float* conv_b    = (const float*)d_in[5];
    const float* x_proj_w  = (const float*)d_in[6];
    const float* dt_proj_w = (const float*)d_in[7];
    const float* dt_proj_b = (const float*)d_in[8];
    const float* A_log     = (const float*)d_in[9];
    const float* Dp        = (const float*)d_in[10];
    const float* out_proj_w= (const float*)d_in[11];
    const float* norm_w    = (const float*)d_in[12];
    float* h = (float*)d_out;

    float *p_u, *p_xz, *p_y;
    __nv_bfloat16 *p_act3, *p_w3;
    cudaGetSymbolAddress((void**)&p_u,    g_u);
    cudaGetSymbolAddress((void**)&p_xz,   g_xz);
    cudaGetSymbolAddress((void**)&p_y,    g_y);
    cudaGetSymbolAddress((void**)&p_act3, g_act3);
    cudaGetSymbolAddress((void**)&p_w3,   g_w3);

    k_embed<<<NROW, DM>>>(x, emb_w, emb_b, h);

    for (int l = 0; l < 2; ++l) {
        const float* inw = in_proj_w + (size_t)l * (2*DI) * DM;
        const float* cw  = conv_w   + (size_t)l * DI * 4;
        const float* cb  = conv_b   + (size_t)l * DI;
        const float* xpw = x_proj_w + (size_t)l * 48 * DI;
        const float* dtw = dt_proj_w+ (size_t)l * DI * DR;
        const float* dtb = dt_proj_b+ (size_t)l * DI;
        const float* al  = A_log    + (size_t)l * DI * DS;
        const float* dp  = Dp       + (size_t)l * DI;
        const float* ow  = out_proj_w + (size_t)l * DM * DI;
        const float* nw  = norm_w   + (size_t)l * DM;

        k_rmsnorm<<<NROW, DM>>>(h, nw);

        // --- GEMM1: xz = u @ in_w^T : M=8192, N=1024, K=256 (K3=768) ---
        k_cvt<<<(NROW*DM)/256, 256>>>(p_u, p_act3, DM, 0);
        k_cvt<<<((2*DI)*DM)/256, 256>>>(inw, p_w3, DM, 1);
        {
            dim3 grid((2*DI)/128, NROW/128);
            k_mgemm<128,false><<<grid, 256>>>(p_act3, p_w3, p_xz, 2*DI, 3*DM);
        }

        k_conv<<<(NROW*DI)/256, 256>>>(cw, cb);
        k_xproj<<<NROW/8, 256>>>(xpw, dtw, dtb);
        k_scan<<<(Bq*(DI/2)*32)/128, 128>>>(al, dp);

        // --- GEMM2: h += y @ ow^T : M=8192, N=256, K=512 (K3=1536) ---
        k_cvt<<<(NROW*DI)/256, 256>>>(p_y, p_act3, DI, 0);
        k_cvt<<<(DM*DI)/256, 256>>>(ow, p_w3, DI, 1);
        {
            dim3 grid(DM/64, NROW/128);
            k_mgemm<64,true><<<grid, 256>>>(p_act3, p_w3, h, DM, 3*DI);
        }
    }
}

// round 9
// speedup vs baseline: 2.2266x; 1.0772x over previous
#include <cuda_runtime.h>
#include <cuda_bf16.h>
#include <cstdint>
#include <math.h>

#define Bq 4
#define Wd 2048
#define DM 256
#define DI 512
#define DS 16
#define DR 16
#define NROW (Bq*Wd)   // 8192
#define NCHK 16        // scan chunks
#define CLEN (Wd/NCHK) // 128 steps per chunk

// ---------------- static scratch ----------------
__device__ float g_xz[NROW*2*DI];
__device__ float g_xs[NROW*DI];
__device__ float g_dbc[NROW*48];
__device__ float g_delta[NROW*DI];
__device__ float g_y[NROW*DI];
__device__ float g_hend[Bq*256*NCHK*32];
__device__ float g_h0[Bq*256*NCHK*32];
__device__ float g_sumd[Bq*256*NCHK*2];
__device__ __nv_bfloat16 g_act3[(size_t)NROW*1536];
__device__ __nv_bfloat16 g_w3[(size_t)1024*1536];

__device__ __forceinline__ uint32_t smem_u32(const void* p) {
    uint32_t a;
    asm("{ .reg .u64 t; cvta.to.shared.u64 t, %1; cvt.u32.u64 %0, t; }"
        : "=r"(a) : "l"(p));
    return a;
}
__device__ __forceinline__ void ldsm4(uint32_t& r0, uint32_t& r1, uint32_t& r2,
                                      uint32_t& r3, uint32_t addr) {
    asm volatile("ldmatrix.sync.aligned.m8n8.x4.shared.b16 {%0,%1,%2,%3}, [%4];"
                 : "=r"(r0), "=r"(r1), "=r"(r2), "=r"(r3) : "r"(addr));
}
__device__ __forceinline__ void mma_bf16(float* d, const uint32_t* a, const uint32_t* b) {
    asm volatile("mma.sync.aligned.m16n8k16.row.col.f32.bf16.bf16.f32 "
                 "{%0,%1,%2,%3}, {%4,%5,%6,%7}, {%8,%9}, {%0,%1,%2,%3};"
                 : "+f"(d[0]), "+f"(d[1]), "+f"(d[2]), "+f"(d[3])
                 : "r"(a[0]), "r"(a[1]), "r"(a[2]), "r"(a[3]), "r"(b[0]), "r"(b[1]));
}

// ---------------- embed ----------------
__global__ void k_embed(const float* __restrict__ x, const float* __restrict__ ew,
                        const float* __restrict__ eb, float* __restrict__ h) {
    int r = blockIdx.x, d = threadIdx.x;
    h[r*DM + d] = fmaf(x[r], ew[d], eb[d]);
}

// ---------------- rmsnorm + split-convert activations (K=DM) -> g_act3 --------------
__global__ void k_rmscvt(const float* __restrict__ h, const float* __restrict__ w,
                         __nv_bfloat16* __restrict__ dst) {
    int r = blockIdx.x, d = threadIdx.x;
    float v = h[r*DM + d];
    float ss = v*v;
    #pragma unroll
    for (int o = 16; o; o >>= 1) ss += __shfl_xor_sync(0xffffffffu, ss, o);
    __shared__ float sh[8];
    int wid = d >> 5, lane = d & 31;
    if (lane == 0) sh[wid] = ss;
    __syncthreads();
    if (wid == 0) {
        float t = (lane < 8) ? sh[lane] : 0.f;
        #pragma unroll
        for (int o = 4; o; o >>= 1) t += __shfl_xor_sync(0xffffffffu, t, o);
        if (lane == 0) sh[0] = t;
    }
    __syncthreads();
    float inv = rsqrtf(sh[0] * (1.0f/DM) + 1e-5f);
    float x = v * inv * w[d];
    __nv_bfloat16 hi = __float2bfloat16(x);
    __nv_bfloat16 lo = __float2bfloat16(x - __bfloat162float(hi));
    size_t b = (size_t)r * 3 * DM;
    dst[b + d] = hi;
    dst[b + DM + d] = hi;
    dst[b + 2*DM + d] = lo;
}

// ---------------- split fp32 -> bf16 concatenation ----------------
__global__ void k_cvt(const float* __restrict__ src, __nv_bfloat16* __restrict__ dst,
                      int K, int s1lo) {
    int idx = blockIdx.x * blockDim.x + threadIdx.x;
    int r = idx / K, k = idx % K;
    float x = src[idx];
    __nv_bfloat16 hi = __float2bfloat16(x);
    __nv_bfloat16 lo = __float2bfloat16(x - __bfloat162float(hi));
    size_t b = (size_t)r * 3 * K;
    dst[b + k] = hi;
    dst[b + K + k]   = s1lo ? lo : hi;
    dst[b + 2*K + k] = s1lo ? hi : lo;
}

// ---------------- mma.sync bf16 GEMM ----------------
template<int BN, bool ACC>
__global__ __launch_bounds__(256) void k_mgemm(
    const __nv_bfloat16* __restrict__ A3, const __nv_bfloat16* __restrict__ B3,
    float* __restrict__ C, int N, int K3)
{
    constexpr int BM = 128, BK = 32;
    constexpr int LD = 40;
    constexpr int NI = BN / 16;
    constexpr int AV = (BM*BK)/(8*256);
    constexpr int BV = (BN*BK)/(8*256);
    __shared__ __nv_bfloat16 smA[2][BM*LD];
    __shared__ __nv_bfloat16 smB[2][BN*LD];

    const int tid = threadIdx.x;
    const int wid = tid >> 5, lane = tid & 31;
    const int wm = (wid & 3) * 32;
    const int wn = (wid >> 2) * (BN/2);
    const int m0 = blockIdx.y * BM, n0 = blockIdx.x * BN;
    const int nch = K3 / BK;

    float acc[2][NI][4];
    #pragma unroll
    for (int mi = 0; mi < 2; mi++)
        #pragma unroll
        for (int ni = 0; ni < NI; ni++)
            #pragma unroll
            for (int j = 0; j < 4; j++) acc[mi][ni][j] = 0.f;

    int arow[AV], aq[AV], brow[BV], bq[BV];
    #pragma unroll
    for (int i = 0; i < AV; i++) { int idx = tid + 256*i; arow[i] = idx >> 2; aq[i] = idx & 3; }
    #pragma unroll
    for (int i = 0; i < BV; i++) { int idx = tid + 256*i; brow[i] = idx >> 2; bq[i] = idx & 3; }

    #pragma unroll
    for (int i = 0; i < AV; i++)
        *(uint4*)&smA[0][arow[i]*LD + aq[i]*8] =
            *(const uint4*)(A3 + (size_t)(m0+arow[i])*K3 + aq[i]*8);
    #pragma unroll
    for (int i = 0; i < BV; i++)
        *(uint4*)&smB[0][brow[i]*LD + bq[i]*8] =
            *(const uint4*)(B3 + (size_t)(n0+brow[i])*K3 + bq[i]*8);
    __syncthreads();

    for (int c = 0; c < nch; c++) {
        const int buf = c & 1;
        const bool more = (c + 1 < nch);
        uint4 va[AV], vb[BV];
        if (more) {
            int k0 = (c+1) * BK;
            #pragma unroll
            for (int i = 0; i < AV; i++)
                va[i] = *(const uint4*)(A3 + (size_t)(m0+arow[i])*K3 + k0 + aq[i]*8);
            #pragma unroll
            for (int i = 0; i < BV; i++)
                vb[i] = *(const uint4*)(B3 + (size_t)(n0+brow[i])*K3 + k0 + bq[i]*8);
        }

        #pragma unroll
        for (int k16 = 0; k16 < 2; k16++) {
            const int k0 = k16 * 16;
            uint32_t a[2][4];
            #pragma unroll
            for (int mi = 0; mi < 2; mi++) {
                uint32_t addr = smem_u32(
                    &smA[buf][(wm + mi*16 + (lane & 15))*LD + k0 + (lane >> 4)*8]);
                ldsm4(a[mi][0], a[mi][1], a[mi][2], a[mi][3], addr);
            }
            uint32_t b[NI][2];
            #pragma unroll
            for (int ng = 0; ng < NI/2; ng++) {
                uint32_t r0, r1, r2, r3;
                uint32_t addr = smem_u32(
                    &smB[buf][(wn + ng*16 + (lane & 15))*LD + k0 + (lane >> 4)*8]);
                ldsm4(r0, r1, r2, r3, addr);
                b[2*ng][0] = r0; b[2*ng][1] = r2;
                b[2*ng+1][0] = r1; b[2*ng+1][1] = r3;
            }
            #pragma unroll
            for (int mi = 0; mi < 2; mi++)
                #pragma unroll
                for (int ni = 0; ni < NI; ni++)
                    mma_bf16(acc[mi][ni], a[mi], b[ni]);
        }

        if (more) {
            int nb = buf ^ 1;
            #pragma unroll
            for (int i = 0; i < AV; i++)
                *(uint4*)&smA[nb][arow[i]*LD + aq[i]*8] = va[i];
            #pragma unroll
            for (int i = 0; i < BV; i++)
                *(uint4*)&smB[nb][brow[i]*LD + bq[i]*8] = vb[i];
        }
        __syncthreads();
    }

    #pragma unroll
    for (int mi = 0; mi < 2; mi++) {
        #pragma unroll
        for (int ni = 0; ni < NI; ni++) {
            int m = m0 + wm + mi*16 + (lane >> 2);
            int n = n0 + wn + ni*8 + (lane & 3)*2;
            float2* p0 = (float2*)&C[(size_t)m*N + n];
            float2* p1 = (float2*)&C[(size_t)(m+8)*N + n];
            float2 v0 = make_float2(acc[mi][ni][0], acc[mi][ni][1]);
            float2 v1 = make_float2(acc[mi][ni][2], acc[mi][ni][3]);
            if (ACC) {
                float2 o0 = *p0, o1 = *p1;
                v0.x += o0.x; v0.y += o0.y; v1.x += o1.x; v1.y += o1.y;
            }
            *p0 = v0; *p1 = v1;
        }
    }
}

// ---------------- causal depthwise conv (k=4) + silu ----------------
__global__ void k_conv(const float* __restrict__ cw, const float* __restrict__ cb) {
    int idx = blockIdx.x * blockDim.x + threadIdx.x;
    int e = idx % DI;
    int row = idx / DI;
    int w = row % Wd;
    float acc = cb[e];
    #pragma unroll
    for (int k = 0; k < 4; k++) {
        int ww = w + k - 3;
        if (ww >= 0) acc = fmaf(cw[e*4 + k], g_xz[(size_t)(row + k - 3)*(2*DI) + e], acc);
    }
    g_xs[idx] = acc / (1.f + __expf(-acc));
}

// ---------------- x_proj + dt_proj + softplus (fused) ----------------
__global__ __launch_bounds__(256) void k_xproj(const float* __restrict__ xpw,
                                               const float* __restrict__ dtw,
                                               const float* __restrict__ dtb) {
    __shared__ float sx[8][DI];
    __shared__ float sdt[8][DR];
    int r0 = blockIdx.x * 8;
    #pragma unroll
    for (int i = 0; i < 4; i++) {
        int idx = threadIdx.x + 256*i;
        int rr = idx / (DI/4);
        int c4 = idx % (DI/4);
        *(float4*)&sx[rr][c4*4] = *(const float4*)&g_xs[(size_t)(r0+rr)*DI + c4*4];
    }
    __syncthreads();
    int warp = threadIdx.x >> 5, lane = threadIdx.x & 31;
    for (int jj = 0; jj < 6; jj++) {
        int j = warp*6 + jj;
        float wreg[16];
        #pragma unroll
        for (int i = 0; i < 16; i++) wreg[i] = xpw[(size_t)j*DI + lane + 32*i];
        #pragma unroll
        for (int rr = 0; rr < 8; rr++) {
            float s = 0.f;
            #pragma unroll
            for (int i = 0; i < 16; i++) s = fmaf(wreg[i], sx[rr][lane + 32*i], s);
            #pragma unroll
            for (int o = 16; o; o >>= 1) s += __shfl_xor_sync(0xffffffffu, s, o);
            if (lane == 0) {
                if (j < DR) sdt[rr][j] = s;
                else        g_dbc[(size_t)(r0+rr)*48 + j] = s;
            }
        }
    }
    __syncthreads();
    #pragma unroll
    for (int it = 0; it < 16; it++) {
        int o = threadIdx.x + 256*it;
        int rr = o >> 9;
        int d = o & (DI-1);
        float acc = dtb[d];
        #pragma unroll
        for (int j = 0; j < DR; j++) acc = fmaf(sdt[rr][j], dtw[d*DR + j], acc);
        float e = __expf(-fabsf(acc));
        float sp = fmaxf(acc, 0.f) + __logf(1.f + e);
        g_delta[(size_t)(r0+rr)*DI + d] = sp;
    }
}

// ---------------- scan phase A: per-chunk (h_end, sum_delta) from h0=0 ---------------
__global__ __launch_bounds__(128) void k_scanA(const float* __restrict__ A_log) {
    int gw = (blockIdx.x * blockDim.x + threadIdx.x) >> 5;   // 0..16383
    int lane = threadIdx.x & 31;
    int chunk = gw & (NCHK-1);
    int dpair = (gw >> 4) & 255;
    int b = gw >> 12;
    int s = lane & 15, dch = lane >> 4;
    int dd = dpair*2 + dch;

    float Av = -expf(A_log[dd*DS + s]);
    size_t toff = (size_t)chunk * CLEN;
    const float* pd = g_delta + (size_t)b*Wd*DI + dd + toff*DI;
    const float* pu = g_xs    + (size_t)b*Wd*DI + dd + toff*DI;
    const float* pB = g_dbc   + (size_t)b*Wd*48 + DR + s + toff*48;

    float h = 0.f, sd = 0.f;
    #pragma unroll 4
    for (int t = 0; t < CLEN; t++) {
        float dc = pd[(size_t)t*DI];
        float uc = pu[(size_t)t*DI];
        float Bc = pB[(size_t)t*48];
        float dA = __expf(dc * Av);
        h = fmaf(dA, h, dc * Bc * uc);
        sd += dc;
    }
    size_t base = (size_t)(b*256 + dpair)*NCHK + chunk;
    g_hend[base*32 + lane] = h;
    if (s == 0) g_sumd[base*2 + dch] = sd;
}

// ---------------- scan phase B: serial chunk-prefix composition ----------------------
__global__ __launch_bounds__(128) void k_scanB(const float* __restrict__ A_log) {
    int gw = (blockIdx.x * blockDim.x + threadIdx.x) >> 5;   // 0..1023
    int lane = threadIdx.x & 31;
    int dpair = gw & 255;
    int b = gw >> 8;
    int s = lane & 15, dch = lane >> 4;
    int dd = dpair*2 + dch;

    float Av = -expf(A_log[dd*DS + s]);
    size_t base0 = (size_t)(b*256 + dpair)*NCHK;
    float H = 0.f;
    #pragma unroll
    for (int c = 0; c < NCHK; c++) {
        g_h0[(base0+c)*32 + lane] = H;
        float sd = g_sumd[(base0+c)*2 + dch];
        float he = g_hend[(base0+c)*32 + lane];
        H = fmaf(__expf(Av * sd), H, he);
    }
}

// ---------------- scan phase C: re-run chunk from corrected h0, full epilogue --------
__global__ __launch_bounds__(128) void k_scanC(const float* __restrict__ A_log,
                                               const float* __restrict__ Dp) {
    int gw = (blockIdx.x * blockDim.x + threadIdx.x) >> 5;
    int lane = threadIdx.x & 31;
    int chunk = gw & (NCHK-1);
    int dpair = (gw >> 4) & 255;
    int b = gw >> 12;
    int s = lane & 15, dch = lane >> 4;
    int dd = dpair*2 + dch;

    float Av = -expf(A_log[dd*DS + s]);
    float Dpv = Dp[dd];
    size_t toff = (size_t)chunk * CLEN;
    const float* pd = g_delta + (size_t)b*Wd*DI + dd + toff*DI;
    const float* pu = g_xs    + (size_t)b*Wd*DI + dd + toff*DI;
    const float* pB = g_dbc   + (size_t)b*Wd*48 + DR + s + toff*48;
    const float* pC = g_dbc   + (size_t)b*Wd*48 + DR + DS + s + toff*48;
    const float* pz = g_xz    + (size_t)b*Wd*(2*DI) + DI + dd + toff*(2*DI);
    float* py = g_y + (size_t)b*Wd*DI + dd + toff*DI;

    size_t base = (size_t)(b*256 + dpair)*NCHK + chunk;
    float hst = g_h0[base*32 + lane];

    #pragma unroll 4
    for (int t = 0; t < CLEN; t++) {
        float dc = pd[(size_t)t*DI];
        float uc = pu[(size_t)t*DI];
        float Bc = pB[(size_t)t*48];
        float Cc = pC[(size_t)t*48];
        float zc = pz[(size_t)t*(2*DI)];
        float dA = __expf(dc * Av);
        hst = fmaf(dA, hst, dc * Bc * uc);
        float yv = hst * Cc;
        yv += __shfl_xor_sync(0xffffffffu, yv, 8);
        yv += __shfl_xor_sync(0xffffffffu, yv, 4);
        yv += __shfl_xor_sync(0xffffffffu, yv, 2);
        yv += __shfl_xor_sync(0xffffffffu, yv, 1);
        if (s == 0) {
            float g = zc / (1.f + __expf(-zc));
            py[(size_t)t*DI] = fmaf(uc, Dpv, yv) * g;
        }
    }
}

// ---------------- host launch ----------------
extern "C" void kernel_launch(void* const* d_in, const int* in_sizes, int n_in,
                              void* d_out, int out_size) {
    const float* x         = (const float*)d_in[0];
    const float* emb_w     = (const float*)d_in[1];
    const float* emb_b     = (const float*)d_in[2];
    const float* in_proj_w = (const float*)d_in[3];
    const float* conv_w    = (const float*)d_in[4];
    const float* conv_b    = (const float*)d_in[5];
    const float* x_proj_w  = (const float*)d_in[6];
    const float* dt_proj_w = (const float*)d_in[7];
    const float* dt_proj_b = (const float*)d_in[8];
    const float* A_log     = (const float*)d_in[9];
    const float* Dp        = (const float*)d_in[10];
    const float* out_proj_w= (const float*)d_in[11];
    const float* norm_w    = (const float*)d_in[12];
    float* h = (float*)d_out;

    float *p_xz, *p_y;
    __nv_bfloat16 *p_act3, *p_w3;
    cudaGetSymbolAddress((void**)&p_xz,   g_xz);
    cudaGetSymbolAddress((void**)&p_y,    g_y);
    cudaGetSymbolAddress((void**)&p_act3, g_act3);
    cudaGetSymbolAddress((void**)&p_w3,   g_w3);

    k_embed<<<NROW, DM>>>(x, emb_w, emb_b, h);

    for (int l = 0; l < 2; ++l) {
        const float* inw = in_proj_w + (size_t)l * (2*DI) * DM;
        const float* cw  = conv_w   + (size_t)l * DI * 4;
        const float* cb  = conv_b   + (size_t)l * DI;
        const float* xpw = x_proj_w + (size_t)l * 48 * DI;
        const float* dtw = dt_proj_w+ (size_t)l * DI * DR;
        const float* dtb = dt_proj_b+ (size_t)l * DI;
        const float* al  = A_log    + (size_t)l * DI * DS;
        const float* dp  = Dp       + (size_t)l * DI;
        const float* ow  = out_proj_w + (size_t)l * DM * DI;
        const float* nw  = norm_w   + (size_t)l * DM;

        // --- GEMM1: xz = rmsnorm(h) @ in_w^T (split bf16 tensor-core) ---
        k_rmscvt<<<NROW, DM>>>(h, nw, p_act3);
        k_cvt<<<((2*DI)*DM)/256, 256>>>(inw, p_w3, DM, 1);
        {
            dim3 grid((2*DI)/128, NROW/128);
            k_mgemm<128,false><<<grid, 256>>>(p_act3, p_w3, p_xz, 2*DI, 3*DM);
        }

        k_conv<<<(NROW*DI)/256, 256>>>(cw, cb);
        k_xproj<<<NROW/8, 256>>>(xpw, dtw, dtb);

        // --- scan: 3-phase chunk-parallel ---
        k_scanA<<<(Bq*256*NCHK*32)/128, 128>>>(al);
        k_scanB<<<(Bq*256*32)/128, 128>>>(al);
        k_scanC<<<(Bq*256*NCHK*32)/128, 128>>>(al, dp);

        // --- GEMM2: h += y @ ow^T ---
        k_cvt<<<(NROW*DI)/256, 256>>>(p_y, p_act3, DI, 0);
        k_cvt<<<(DM*DI)/256, 256>>>(ow, p_w3, DI, 1);
        {
            dim3 grid(DM/64, NROW/128);
            k_mgemm<64,true><<<grid, 256>>>(p_act3, p_w3, h, DM, 3*DI);
        }
    }
}

// round 10
// speedup vs baseline: 2.5912x; 1.1637x over previous
#include <cuda_runtime.h>
#include <cuda_bf16.h>
#include <cstdint>
#include <math.h>

#define Bq 4
#define Wd 2048
#define DM 256
#define DI 512
#define DS 16
#define DR 16
#define NROW (Bq*Wd)   // 8192
#define NCHK 16
#define CLEN (Wd/NCHK) // 128

// ---------------- static scratch ----------------
__device__ float g_xz[NROW*2*DI];
__device__ float g_xs[NROW*DI];
__device__ float g_dbc[NROW*48];
__device__ float g_delta[NROW*DI];
__device__ float g_hend[Bq*256*NCHK*32];
__device__ float g_h0[Bq*256*NCHK*32];
__device__ float g_sumd[Bq*256*NCHK*2];
__device__ __nv_bfloat16 g_act3[(size_t)NROW*1536];
__device__ __nv_bfloat16 g_w3[(size_t)1024*1536];

__device__ __forceinline__ uint32_t smem_u32(const void* p) {
    uint32_t a;
    asm("{ .reg .u64 t; cvta.to.shared.u64 t, %1; cvt.u32.u64 %0, t; }"
        : "=r"(a) : "l"(p));
    return a;
}
__device__ __forceinline__ void ldsm4(uint32_t& r0, uint32_t& r1, uint32_t& r2,
                                      uint32_t& r3, uint32_t addr) {
    asm volatile("ldmatrix.sync.aligned.m8n8.x4.shared.b16 {%0,%1,%2,%3}, [%4];"
                 : "=r"(r0), "=r"(r1), "=r"(r2), "=r"(r3) : "r"(addr));
}
__device__ __forceinline__ void mma_bf16(float* d, const uint32_t* a, const uint32_t* b) {
    asm volatile("mma.sync.aligned.m16n8k16.row.col.f32.bf16.bf16.f32 "
                 "{%0,%1,%2,%3}, {%4,%5,%6,%7}, {%8,%9}, {%0,%1,%2,%3};"
                 : "+f"(d[0]), "+f"(d[1]), "+f"(d[2]), "+f"(d[3])
                 : "r"(a[0]), "r"(a[1]), "r"(a[2]), "r"(a[3]), "r"(b[0]), "r"(b[1]));
}
__device__ __forceinline__ void cpa16(uint32_t sm, const void* g) {
    asm volatile("cp.async.cg.shared.global [%0], [%1], 16;" :: "r"(sm), "l"(g));
}
__device__ __forceinline__ void cpa_commit() {
    asm volatile("cp.async.commit_group;" ::: "memory");
}
template<int N>
__device__ __forceinline__ void cpa_wait() {
    asm volatile("cp.async.wait_group %0;" :: "n"(N) : "memory");
}

// ---------------- embed ----------------
__global__ void k_embed(const float* __restrict__ x, const float* __restrict__ ew,
                        const float* __restrict__ eb, float* __restrict__ h) {
    int r = blockIdx.x, d = threadIdx.x;
    h[r*DM + d] = fmaf(x[r], ew[d], eb[d]);
}

// ---------------- rmsnorm + split-convert activations -> g_act3 ----------------
__global__ void k_rmscvt(const float* __restrict__ h, const float* __restrict__ w,
                         __nv_bfloat16* __restrict__ dst) {
    int r = blockIdx.x, d = threadIdx.x;
    float v = h[r*DM + d];
    float ss = v*v;
    #pragma unroll
    for (int o = 16; o; o >>= 1) ss += __shfl_xor_sync(0xffffffffu, ss, o);
    __shared__ float sh[8];
    int wid = d >> 5, lane = d & 31;
    if (lane == 0) sh[wid] = ss;
    __syncthreads();
    if (wid == 0) {
        float t = (lane < 8) ? sh[lane] : 0.f;
        #pragma unroll
        for (int o = 4; o; o >>= 1) t += __shfl_xor_sync(0xffffffffu, t, o);
        if (lane == 0) sh[0] = t;
    }
    __syncthreads();
    float inv = rsqrtf(sh[0] * (1.0f/DM) + 1e-5f);
    float x = v * inv * w[d];
    __nv_bfloat16 hi = __float2bfloat16(x);
    __nv_bfloat16 lo = __float2bfloat16(x - __bfloat162float(hi));
    size_t b = (size_t)r * 3 * DM;
    dst[b + d] = hi;
    dst[b + DM + d] = hi;
    dst[b + 2*DM + d] = lo;
}

// ---------------- split fp32 -> bf16 (weights) ----------------
__global__ void k_cvt(const float* __restrict__ src, __nv_bfloat16* __restrict__ dst,
                      int K, int s1lo) {
    int idx = blockIdx.x * blockDim.x + threadIdx.x;
    int r = idx / K, k = idx % K;
    float x = src[idx];
    __nv_bfloat16 hi = __float2bfloat16(x);
    __nv_bfloat16 lo = __float2bfloat16(x - __bfloat162float(hi));
    size_t b = (size_t)r * 3 * K;
    dst[b + k] = hi;
    dst[b + K + k]   = s1lo ? lo : hi;
    dst[b + 2*K + k] = s1lo ? hi : lo;
}

// ---------------- mma.sync bf16 GEMM, cp.async double-buffered ----------------
template<int BN, bool ACC>
__global__ __launch_bounds__(256) void k_mgemm(
    const __nv_bfloat16* __restrict__ A3, const __nv_bfloat16* __restrict__ B3,
    float* __restrict__ C, int N, int K3)
{
    constexpr int BM = 128, BK = 32;
    constexpr int LD = 40;
    constexpr int NI = BN / 16;
    constexpr int AV = (BM*BK)/(8*256);   // 2
    constexpr int BV = (BN*BK)/(8*256);   // 2 or 1
    __shared__ __nv_bfloat16 smA[2][BM*LD];
    __shared__ __nv_bfloat16 smB[2][BN*LD];

    const int tid = threadIdx.x;
    const int wid = tid >> 5, lane = tid & 31;
    const int wm = (wid & 3) * 32;
    const int wn = (wid >> 2) * (BN/2);
    const int m0 = blockIdx.y * BM, n0 = blockIdx.x * BN;
    const int nch = K3 / BK;

    float acc[2][NI][4];
    #pragma unroll
    for (int mi = 0; mi < 2; mi++)
        #pragma unroll
        for (int ni = 0; ni < NI; ni++)
            #pragma unroll
            for (int j = 0; j < 4; j++) acc[mi][ni][j] = 0.f;

    int arow[AV], aq[AV], brow[BV], bq[BV];
    #pragma unroll
    for (int i = 0; i < AV; i++) { int idx = tid + 256*i; arow[i] = idx >> 2; aq[i] = idx & 3; }
    #pragma unroll
    for (int i = 0; i < BV; i++) { int idx = tid + 256*i; brow[i] = idx >> 2; bq[i] = idx & 3; }

    // issue chunk 0
    #pragma unroll
    for (int i = 0; i < AV; i++)
        cpa16(smem_u32(&smA[0][arow[i]*LD + aq[i]*8]),
              A3 + (size_t)(m0+arow[i])*K3 + aq[i]*8);
    #pragma unroll
    for (int i = 0; i < BV; i++)
        cpa16(smem_u32(&smB[0][brow[i]*LD + bq[i]*8]),
              B3 + (size_t)(n0+brow[i])*K3 + bq[i]*8);
    cpa_commit();

    for (int c = 0; c < nch; c++) {
        const int buf = c & 1;
        const bool more = (c + 1 < nch);
        if (more) {
            int k0 = (c+1) * BK;
            int nb = buf ^ 1;
            #pragma unroll
            for (int i = 0; i < AV; i++)
                cpa16(smem_u32(&smA[nb][arow[i]*LD + aq[i]*8]),
                      A3 + (size_t)(m0+arow[i])*K3 + k0 + aq[i]*8);
            #pragma unroll
            for (int i = 0; i < BV; i++)
                cpa16(smem_u32(&smB[nb][brow[i]*LD + bq[i]*8]),
                      B3 + (size_t)(n0+brow[i])*K3 + k0 + bq[i]*8);
            cpa_commit();
            cpa_wait<1>();
        } else {
            cpa_wait<0>();
        }
        __syncthreads();

        #pragma unroll
        for (int k16 = 0; k16 < 2; k16++) {
            const int k0 = k16 * 16;
            uint32_t a[2][4];
            #pragma unroll
            for (int mi = 0; mi < 2; mi++) {
                uint32_t addr = smem_u32(
                    &smA[buf][(wm + mi*16 + (lane & 15))*LD + k0 + (lane >> 4)*8]);
                ldsm4(a[mi][0], a[mi][1], a[mi][2], a[mi][3], addr);
            }
            uint32_t b[NI][2];
            #pragma unroll
            for (int ng = 0; ng < NI/2; ng++) {
                uint32_t r0, r1, r2, r3;
                uint32_t addr = smem_u32(
                    &smB[buf][(wn + ng*16 + (lane & 15))*LD + k0 + (lane >> 4)*8]);
                ldsm4(r0, r1, r2, r3, addr);
                b[2*ng][0] = r0; b[2*ng][1] = r2;
                b[2*ng+1][0] = r1; b[2*ng+1][1] = r3;
            }
            #pragma unroll
            for (int mi = 0; mi < 2; mi++)
                #pragma unroll
                for (int ni = 0; ni < NI; ni++)
                    mma_bf16(acc[mi][ni], a[mi], b[ni]);
        }
        __syncthreads();
    }

    #pragma unroll
    for (int mi = 0; mi < 2; mi++) {
        #pragma unroll
        for (int ni = 0; ni < NI; ni++) {
            int m = m0 + wm + mi*16 + (lane >> 2);
            int n = n0 + wn + ni*8 + (lane & 3)*2;
            float2* p0 = (float2*)&C[(size_t)m*N + n];
            float2* p1 = (float2*)&C[(size_t)(m+8)*N + n];
            float2 v0 = make_float2(acc[mi][ni][0], acc[mi][ni][1]);
            float2 v1 = make_float2(acc[mi][ni][2], acc[mi][ni][3]);
            if (ACC) {
                float2 o0 = *p0, o1 = *p1;
                v0.x += o0.x; v0.y += o0.y; v1.x += o1.x; v1.y += o1.y;
            }
            *p0 = v0; *p1 = v1;
        }
    }
}

// ---------------- conv+silu + x_proj + dt_proj + softplus (fully fused) -------------
__global__ __launch_bounds__(256) void k_xprojc(
    const float* __restrict__ cw, const float* __restrict__ cb,
    const float* __restrict__ xpw, const float* __restrict__ dtw,
    const float* __restrict__ dtb)
{
    __shared__ float sraw[11][DI];   // xz x-part rows r0-3 .. r0+7 (22 KB)
    __shared__ float sx[8][DI];      // conv+silu output (16 KB)
    __shared__ float sdt[8][DR];
    const int r0 = blockIdx.x * 8;
    const int w0 = r0 % Wd;          // chunk never crosses batch boundary (8 | Wd)

    // load 11 rows (zero-pad before batch start)
    for (int idx = threadIdx.x; idx < 11*(DI/4); idx += 256) {
        int ro = idx / (DI/4);
        int c4 = idx % (DI/4);
        float4 v = make_float4(0.f, 0.f, 0.f, 0.f);
        if (w0 - 3 + ro >= 0)
            v = *(const float4*)&g_xz[(size_t)(r0 - 3 + ro)*(2*DI) + c4*4];
        *(float4*)&sraw[ro][c4*4] = v;
    }
    __syncthreads();

    // conv (k=4) + silu -> sx, also write g_xs for the scan
    #pragma unroll
    for (int it = 0; it < 16; it++) {
        int o = threadIdx.x + 256*it;
        int rr = o >> 9;
        int e = o & (DI-1);
        float acc = cb[e];
        #pragma unroll
        for (int k = 0; k < 4; k++)
            acc = fmaf(cw[e*4 + k], sraw[rr + k][e], acc);
        float v = acc / (1.f + __expf(-acc));
        sx[rr][e] = v;
        g_xs[(size_t)(r0+rr)*DI + e] = v;
    }
    __syncthreads();

    int warp = threadIdx.x >> 5, lane = threadIdx.x & 31;
    for (int jj = 0; jj < 6; jj++) {
        int j = warp*6 + jj;
        float wreg[16];
        #pragma unroll
        for (int i = 0; i < 16; i++) wreg[i] = xpw[(size_t)j*DI + lane + 32*i];
        #pragma unroll
        for (int rr = 0; rr < 8; rr++) {
            float s = 0.f;
            #pragma unroll
            for (int i = 0; i < 16; i++) s = fmaf(wreg[i], sx[rr][lane + 32*i], s);
            #pragma unroll
            for (int o = 16; o; o >>= 1) s += __shfl_xor_sync(0xffffffffu, s, o);
            if (lane == 0) {
                if (j < DR) sdt[rr][j] = s;
                else        g_dbc[(size_t)(r0+rr)*48 + j] = s;
            }
        }
    }
    __syncthreads();
    #pragma unroll
    for (int it = 0; it < 16; it++) {
        int o = threadIdx.x + 256*it;
        int rr = o >> 9;
        int d = o & (DI-1);
        float acc = dtb[d];
        #pragma unroll
        for (int j = 0; j < DR; j++) acc = fmaf(sdt[rr][j], dtw[d*DR + j], acc);
        float e = __expf(-fabsf(acc));
        float sp = fmaxf(acc, 0.f) + __logf(1.f + e);
        g_delta[(size_t)(r0+rr)*DI + d] = sp;
    }
}

// ---------------- scan phase A ----------------
__global__ __launch_bounds__(128) void k_scanA(const float* __restrict__ A_log) {
    int gw = (blockIdx.x * blockDim.x + threadIdx.x) >> 5;
    int lane = threadIdx.x & 31;
    int chunk = gw & (NCHK-1);
    int dpair = (gw >> 4) & 255;
    int b = gw >> 12;
    int s = lane & 15, dch = lane >> 4;
    int dd = dpair*2 + dch;

    float Av = -expf(A_log[dd*DS + s]);
    size_t toff = (size_t)chunk * CLEN;
    const float* pd = g_delta + (size_t)b*Wd*DI + dd + toff*DI;
    const float* pu = g_xs    + (size_t)b*Wd*DI + dd + toff*DI;
    const float* pB = g_dbc   + (size_t)b*Wd*48 + DR + s + toff*48;

    float h = 0.f, sd = 0.f;
    #pragma unroll 4
    for (int t = 0; t < CLEN; t++) {
        float dc = pd[(size_t)t*DI];
        float uc = pu[(size_t)t*DI];
        float Bc = pB[(size_t)t*48];
        float dA = __expf(dc * Av);
        h = fmaf(dA, h, dc * Bc * uc);
        sd += dc;
    }
    size_t base = (size_t)(b*256 + dpair)*NCHK + chunk;
    g_hend[base*32 + lane] = h;
    if (s == 0) g_sumd[base*2 + dch] = sd;
}

// ---------------- scan phase B ----------------
__global__ __launch_bounds__(128) void k_scanB(const float* __restrict__ A_log) {
    int gw = (blockIdx.x * blockDim.x + threadIdx.x) >> 5;
    int lane = threadIdx.x & 31;
    int dpair = gw & 255;
    int b = gw >> 8;
    int s = lane & 15, dch = lane >> 4;
    int dd = dpair*2 + dch;

    float Av = -expf(A_log[dd*DS + s]);
    size_t base0 = (size_t)(b*256 + dpair)*NCHK;
    float H = 0.f;
    #pragma unroll
    for (int c = 0; c < NCHK; c++) {
        g_h0[(base0+c)*32 + lane] = H;
        float sd = g_sumd[(base0+c)*2 + dch];
        float he = g_hend[(base0+c)*32 + lane];
        H = fmaf(__expf(Av * sd), H, he);
    }
}

// ---------------- scan phase C: full epilogue, writes bf16 split of y -> g_act3 ------
__global__ __launch_bounds__(128) void k_scanC(const float* __restrict__ A_log,
                                               const float* __restrict__ Dp) {
    int gw = (blockIdx.x * blockDim.x + threadIdx.x) >> 5;
    int lane = threadIdx.x & 31;
    int chunk = gw & (NCHK-1);
    int dpair = (gw >> 4) & 255;
    int b = gw >> 12;
    int s = lane & 15, dch = lane >> 4;
    int dd = dpair*2 + dch;

    float Av = -expf(A_log[dd*DS + s]);
    float Dpv = Dp[dd];
    size_t toff = (size_t)chunk * CLEN;
    const float* pd = g_delta + (size_t)b*Wd*DI + dd + toff*DI;
    const float* pu = g_xs    + (size_t)b*Wd*DI + dd + toff*DI;
    const float* pB = g_dbc   + (size_t)b*Wd*48 + DR + s + toff*48;
    const float* pC = g_dbc   + (size_t)b*Wd*48 + DR + DS + s + toff*48;
    const float* pz = g_xz    + (size_t)b*Wd*(2*DI) + DI + dd + toff*(2*DI);

    size_t base = (size_t)(b*256 + dpair)*NCHK + chunk;
    float hst = g_h0[base*32 + lane];
    size_t row0 = (size_t)b*Wd + toff;

    #pragma unroll 4
    for (int t = 0; t < CLEN; t++) {
        float dc = pd[(size_t)t*DI];
        float uc = pu[(size_t)t*DI];
        float Bc = pB[(size_t)t*48];
        float Cc = pC[(size_t)t*48];
        float zc = pz[(size_t)t*(2*DI)];
        float dA = __expf(dc * Av);
        hst = fmaf(dA, hst, dc * Bc * uc);
        float yv = hst * Cc;
        yv += __shfl_xor_sync(0xffffffffu, yv, 8);
        yv += __shfl_xor_sync(0xffffffffu, yv, 4);
        yv += __shfl_xor_sync(0xffffffffu, yv, 2);
        yv += __shfl_xor_sync(0xffffffffu, yv, 1);
        if (s == 0) {
            float g = zc / (1.f + __expf(-zc));
            float val = fmaf(uc, Dpv, yv) * g;
            __nv_bfloat16 hi = __float2bfloat16(val);
            __nv_bfloat16 lo = __float2bfloat16(val - __bfloat162float(hi));
            size_t bb = (row0 + t) * (size_t)(3*DI);
            g_act3[bb + dd] = hi;
            g_act3[bb + DI + dd] = hi;
            g_act3[bb + 2*DI + dd] = lo;
        }
    }
}

// ---------------- host launch ----------------
extern "C" void kernel_launch(void* const* d_in, const int* in_sizes, int n_in,
                              void* d_out, int out_size) {
    const float* x         = (const float*)d_in[0];
    const float* emb_w     = (const float*)d_in[1];
    const float* emb_b     = (const float*)d_in[2];
    const float* in_proj_w = (const float*)d_in[3];
    const float* conv_w    = (const float*)d_in[4];
    const float* conv_b    = (const float*)d_in[5];
    const float* x_proj_w  = (const float*)d_in[6];
    const float* dt_proj_w = (const float*)d_in[7];
    const float* dt_proj_b = (const float*)d_in[8];
    const float* A_log     = (const float*)d_in[9];
    const float* Dp        = (const float*)d_in[10];
    const float* out_proj_w= (const float*)d_in[11];
    const float* norm_w    = (const float*)d_in[12];
    float* h = (float*)d_out;

    float *p_xz;
    __nv_bfloat16 *p_act3, *p_w3;
    cudaGetSymbolAddress((void**)&p_xz,   g_xz);
    cudaGetSymbolAddress((void**)&p_act3, g_act3);
    cudaGetSymbolAddress((void**)&p_w3,   g_w3);

    k_embed<<<NROW, DM>>>(x, emb_w, emb_b, h);

    for (int l = 0; l < 2; ++l) {
        const float* inw = in_proj_w + (size_t)l * (2*DI) * DM;
        const float* cw  = conv_w   + (size_t)l * DI * 4;
        const float* cb  = conv_b   + (size_t)l * DI;
        const float* xpw = x_proj_w + (size_t)l * 48 * DI;
        const float* dtw = dt_proj_w+ (size_t)l * DI * DR;
        const float* dtb = dt_proj_b+ (size_t)l * DI;
        const float* al  = A_log    + (size_t)l * DI * DS;
        const float* dp  = Dp       + (size_t)l * DI;
        const float* ow  = out_proj_w + (size_t)l * DM * DI;
        const float* nw  = norm_w   + (size_t)l * DM;

        // GEMM1: xz = rmsnorm(h) @ in_w^T
        k_rmscvt<<<NROW, DM>>>(h, nw, p_act3);
        k_cvt<<<((2*DI)*DM)/256, 256>>>(inw, p_w3, DM, 1);
        {
            dim3 grid((2*DI)/128, NROW/128);
            k_mgemm<128,false><<<grid, 256>>>(p_act3, p_w3, p_xz, 2*DI, 3*DM);
        }

        // conv+silu+xproj+dt (fused)
        k_xprojc<<<NROW/8, 256>>>(cw, cb, xpw, dtw, dtb);

        // 3-phase scan; phase C emits bf16-split y directly
        k_scanA<<<(Bq*256*NCHK*32)/128, 128>>>(al);
        k_scanB<<<(Bq*256*32)/128, 128>>>(al);
        k_scanC<<<(Bq*256*NCHK*32)/128, 128>>>(al, dp);

        // GEMM2: h += y @ ow^T
        k_cvt<<<(DM*DI)/256, 256>>>(ow, p_w3, DI, 1);
        {
            dim3 grid(DM/64, NROW/128);
            k_mgemm<64,true><<<grid, 256>>>(p_act3, p_w3, h, DM, 3*DI);
        }
    }
}

// round 11
// speedup vs baseline: 2.7856x; 1.0750x over previous
#include <cuda_runtime.h>
#include <cuda_bf16.h>
#include <cstdint>
#include <math.h>

#define Bq 4
#define Wd 2048
#define DM 256
#define DI 512
#define DS 16
#define DR 16
#define NROW (Bq*Wd)   // 8192
#define NCHK 16
#define CLEN (Wd/NCHK) // 128

// ---------------- static scratch ----------------
__device__ float g_xz[NROW*2*DI];                 // GEMM1 output [t][1024]
__device__ float g_xsT[(size_t)Bq*DI*Wd];         // conv+silu, [b][d][t]
__device__ float g_deltaT[(size_t)Bq*DI*Wd];      // softplus(dt), [b][d][t]
__device__ float g_gzT[(size_t)Bq*DI*Wd];         // silu(z), [b][d][t]
__device__ float g_yT[(size_t)Bq*DI*Wd];          // scan output, [b][d][t]
__device__ float g_dbc[NROW*48];
__device__ float g_hend[Bq*256*NCHK*32];
__device__ float g_h0[Bq*256*NCHK*32];
__device__ float g_sumd[Bq*256*NCHK*2];
__device__ __nv_bfloat16 g_act3[(size_t)NROW*1536];
__device__ __nv_bfloat16 g_w3[(size_t)1024*1536];

__device__ __forceinline__ uint32_t smem_u32(const void* p) {
    uint32_t a;
    asm("{ .reg .u64 t; cvta.to.shared.u64 t, %1; cvt.u32.u64 %0, t; }"
        : "=r"(a) : "l"(p));
    return a;
}
__device__ __forceinline__ void ldsm4(uint32_t& r0, uint32_t& r1, uint32_t& r2,
                                      uint32_t& r3, uint32_t addr) {
    asm volatile("ldmatrix.sync.aligned.m8n8.x4.shared.b16 {%0,%1,%2,%3}, [%4];"
                 : "=r"(r0), "=r"(r1), "=r"(r2), "=r"(r3) : "r"(addr));
}
__device__ __forceinline__ void mma_bf16(float* d, const uint32_t* a, const uint32_t* b) {
    asm volatile("mma.sync.aligned.m16n8k16.row.col.f32.bf16.bf16.f32 "
                 "{%0,%1,%2,%3}, {%4,%5,%6,%7}, {%8,%9}, {%0,%1,%2,%3};"
                 : "+f"(d[0]), "+f"(d[1]), "+f"(d[2]), "+f"(d[3])
                 : "r"(a[0]), "r"(a[1]), "r"(a[2]), "r"(a[3]), "r"(b[0]), "r"(b[1]));
}
__device__ __forceinline__ void cpa16(uint32_t sm, const void* g) {
    asm volatile("cp.async.cg.shared.global [%0], [%1], 16;" :: "r"(sm), "l"(g));
}
__device__ __forceinline__ void cpa_commit() {
    asm volatile("cp.async.commit_group;" ::: "memory");
}
template<int N>
__device__ __forceinline__ void cpa_wait() {
    asm volatile("cp.async.wait_group %0;" :: "n"(N) : "memory");
}

// ---------------- embed ----------------
__global__ void k_embed(const float* __restrict__ x, const float* __restrict__ ew,
                        const float* __restrict__ eb, float* __restrict__ h) {
    int r = blockIdx.x, d = threadIdx.x;
    h[r*DM + d] = fmaf(x[r], ew[d], eb[d]);
}

// ---------------- rmsnorm + split-convert activations -> g_act3 ----------------
__global__ void k_rmscvt(const float* __restrict__ h, const float* __restrict__ w,
                         __nv_bfloat16* __restrict__ dst) {
    int r = blockIdx.x, d = threadIdx.x;
    float v = h[r*DM + d];
    float ss = v*v;
    #pragma unroll
    for (int o = 16; o; o >>= 1) ss += __shfl_xor_sync(0xffffffffu, ss, o);
    __shared__ float sh[8];
    int wid = d >> 5, lane = d & 31;
    if (lane == 0) sh[wid] = ss;
    __syncthreads();
    if (wid == 0) {
        float t = (lane < 8) ? sh[lane] : 0.f;
        #pragma unroll
        for (int o = 4; o; o >>= 1) t += __shfl_xor_sync(0xffffffffu, t, o);
        if (lane == 0) sh[0] = t;
    }
    __syncthreads();
    float inv = rsqrtf(sh[0] * (1.0f/DM) + 1e-5f);
    float x = v * inv * w[d];
    __nv_bfloat16 hi = __float2bfloat16(x);
    __nv_bfloat16 lo = __float2bfloat16(x - __bfloat162float(hi));
    size_t b = (size_t)r * 3 * DM;
    dst[b + d] = hi;
    dst[b + DM + d] = hi;
    dst[b + 2*DM + d] = lo;
}

// ---------------- split fp32 -> bf16 (weights) ----------------
__global__ void k_cvt(const float* __restrict__ src, __nv_bfloat16* __restrict__ dst,
                      int K, int s1lo) {
    int idx = blockIdx.x * blockDim.x + threadIdx.x;
    int r = idx / K, k = idx % K;
    float x = src[idx];
    __nv_bfloat16 hi = __float2bfloat16(x);
    __nv_bfloat16 lo = __float2bfloat16(x - __bfloat162float(hi));
    size_t b = (size_t)r * 3 * K;
    dst[b + k] = hi;
    dst[b + K + k]   = s1lo ? lo : hi;
    dst[b + 2*K + k] = s1lo ? hi : lo;
}

// ---------------- mma.sync bf16 GEMM, cp.async double-buffered ----------------
template<int BN, bool ACC>
__global__ __launch_bounds__(256) void k_mgemm(
    const __nv_bfloat16* __restrict__ A3, const __nv_bfloat16* __restrict__ B3,
    float* __restrict__ C, int N, int K3)
{
    constexpr int BM = 128, BK = 32;
    constexpr int LD = 40;
    constexpr int NI = BN / 16;
    constexpr int AV = (BM*BK)/(8*256);
    constexpr int BV = (BN*BK)/(8*256);
    __shared__ __nv_bfloat16 smA[2][BM*LD];
    __shared__ __nv_bfloat16 smB[2][BN*LD];

    const int tid = threadIdx.x;
    const int wid = tid >> 5, lane = tid & 31;
    const int wm = (wid & 3) * 32;
    const int wn = (wid >> 2) * (BN/2);
    const int m0 = blockIdx.y * BM, n0 = blockIdx.x * BN;
    const int nch = K3 / BK;

    float acc[2][NI][4];
    #pragma unroll
    for (int mi = 0; mi < 2; mi++)
        #pragma unroll
        for (int ni = 0; ni < NI; ni++)
            #pragma unroll
            for (int j = 0; j < 4; j++) acc[mi][ni][j] = 0.f;

    int arow[AV], aq[AV], brow[BV], bq[BV];
    #pragma unroll
    for (int i = 0; i < AV; i++) { int idx = tid + 256*i; arow[i] = idx >> 2; aq[i] = idx & 3; }
    #pragma unroll
    for (int i = 0; i < BV; i++) { int idx = tid + 256*i; brow[i] = idx >> 2; bq[i] = idx & 3; }

    #pragma unroll
    for (int i = 0; i < AV; i++)
        cpa16(smem_u32(&smA[0][arow[i]*LD + aq[i]*8]),
              A3 + (size_t)(m0+arow[i])*K3 + aq[i]*8);
    #pragma unroll
    for (int i = 0; i < BV; i++)
        cpa16(smem_u32(&smB[0][brow[i]*LD + bq[i]*8]),
              B3 + (size_t)(n0+brow[i])*K3 + bq[i]*8);
    cpa_commit();

    for (int c = 0; c < nch; c++) {
        const int buf = c & 1;
        const bool more = (c + 1 < nch);
        if (more) {
            int k0 = (c+1) * BK;
            int nb = buf ^ 1;
            #pragma unroll
            for (int i = 0; i < AV; i++)
                cpa16(smem_u32(&smA[nb][arow[i]*LD + aq[i]*8]),
                      A3 + (size_t)(m0+arow[i])*K3 + k0 + aq[i]*8);
            #pragma unroll
            for (int i = 0; i < BV; i++)
                cpa16(smem_u32(&smB[nb][brow[i]*LD + bq[i]*8]),
                      B3 + (size_t)(n0+brow[i])*K3 + k0 + bq[i]*8);
            cpa_commit();
            cpa_wait<1>();
        } else {
            cpa_wait<0>();
        }
        __syncthreads();

        #pragma unroll
        for (int k16 = 0; k16 < 2; k16++) {
            const int k0 = k16 * 16;
            uint32_t a[2][4];
            #pragma unroll
            for (int mi = 0; mi < 2; mi++) {
                uint32_t addr = smem_u32(
                    &smA[buf][(wm + mi*16 + (lane & 15))*LD + k0 + (lane >> 4)*8]);
                ldsm4(a[mi][0], a[mi][1], a[mi][2], a[mi][3], addr);
            }
            uint32_t b[NI][2];
            #pragma unroll
            for (int ng = 0; ng < NI/2; ng++) {
                uint32_t r0, r1, r2, r3;
                uint32_t addr = smem_u32(
                    &smB[buf][(wn + ng*16 + (lane & 15))*LD + k0 + (lane >> 4)*8]);
                ldsm4(r0, r1, r2, r3, addr);
                b[2*ng][0] = r0; b[2*ng][1] = r2;
                b[2*ng+1][0] = r1; b[2*ng+1][1] = r3;
            }
            #pragma unroll
            for (int mi = 0; mi < 2; mi++)
                #pragma unroll
                for (int ni = 0; ni < NI; ni++)
                    mma_bf16(acc[mi][ni], a[mi], b[ni]);
        }
        __syncthreads();
    }

    #pragma unroll
    for (int mi = 0; mi < 2; mi++) {
        #pragma unroll
        for (int ni = 0; ni < NI; ni++) {
            int m = m0 + wm + mi*16 + (lane >> 2);
            int n = n0 + wn + ni*8 + (lane & 3)*2;
            float2* p0 = (float2*)&C[(size_t)m*N + n];
            float2* p1 = (float2*)&C[(size_t)(m+8)*N + n];
            float2 v0 = make_float2(acc[mi][ni][0], acc[mi][ni][1]);
            float2 v1 = make_float2(acc[mi][ni][2], acc[mi][ni][3]);
            if (ACC) {
                float2 o0 = *p0, o1 = *p1;
                v0.x += o0.x; v0.y += o0.y; v1.x += o1.x; v1.y += o1.y;
            }
            *p0 = v0; *p1 = v1;
        }
    }
}

// ------- conv+silu + x_proj + dt_proj + softplus + z-silu, transposed outputs -------
__global__ __launch_bounds__(256) void k_xprojc(
    const float* __restrict__ cw, const float* __restrict__ cb,
    const float* __restrict__ xpw, const float* __restrict__ dtw,
    const float* __restrict__ dtb)
{
    __shared__ float sraw[11][DI];   // 22 KB
    __shared__ float sx[8][DI];      // 16 KB
    __shared__ float sdt[8][DR];
    const int r0 = blockIdx.x * 8;
    const int b = r0 / Wd;
    const int w0 = r0 % Wd;

    for (int idx = threadIdx.x; idx < 11*(DI/4); idx += 256) {
        int ro = idx / (DI/4);
        int c4 = idx % (DI/4);
        float4 v = make_float4(0.f, 0.f, 0.f, 0.f);
        if (w0 - 3 + ro >= 0)
            v = *(const float4*)&g_xz[(size_t)(r0 - 3 + ro)*(2*DI) + c4*4];
        *(float4*)&sraw[ro][c4*4] = v;
    }
    __syncthreads();

    // conv + silu -> sx
    #pragma unroll
    for (int it = 0; it < 16; it++) {
        int o = threadIdx.x + 256*it;
        int rr = o >> 9;
        int e = o & (DI-1);
        float acc = cb[e];
        #pragma unroll
        for (int k = 0; k < 4; k++)
            acc = fmaf(cw[e*4 + k], sraw[rr + k][e], acc);
        sx[rr][e] = acc / (1.f + __expf(-acc));
    }
    __syncthreads();

    // transposed stores: xsT and gzT (silu of z)
    for (int d = threadIdx.x; d < DI; d += 256) {
        float v[8], zv[8];
        #pragma unroll
        for (int rr = 0; rr < 8; rr++) {
            v[rr] = sx[rr][d];
            float z = g_xz[(size_t)(r0+rr)*(2*DI) + DI + d];
            zv[rr] = z / (1.f + __expf(-z));
        }
        float4* px = (float4*)&g_xsT[((size_t)b*DI + d)*Wd + w0];
        px[0] = make_float4(v[0],v[1],v[2],v[3]);
        px[1] = make_float4(v[4],v[5],v[6],v[7]);
        float4* pz = (float4*)&g_gzT[((size_t)b*DI + d)*Wd + w0];
        pz[0] = make_float4(zv[0],zv[1],zv[2],zv[3]);
        pz[1] = make_float4(zv[4],zv[5],zv[6],zv[7]);
    }

    int warp = threadIdx.x >> 5, lane = threadIdx.x & 31;
    for (int jj = 0; jj < 6; jj++) {
        int j = warp*6 + jj;
        float wreg[16];
        #pragma unroll
        for (int i = 0; i < 16; i++) wreg[i] = xpw[(size_t)j*DI + lane + 32*i];
        #pragma unroll
        for (int rr = 0; rr < 8; rr++) {
            float s = 0.f;
            #pragma unroll
            for (int i = 0; i < 16; i++) s = fmaf(wreg[i], sx[rr][lane + 32*i], s);
            #pragma unroll
            for (int o = 16; o; o >>= 1) s += __shfl_xor_sync(0xffffffffu, s, o);
            if (lane == 0) {
                if (j < DR) sdt[rr][j] = s;
                else        g_dbc[(size_t)(r0+rr)*48 + j] = s;
            }
        }
    }
    __syncthreads();

    // dt_proj + softplus, transposed store
    for (int d = threadIdx.x; d < DI; d += 256) {
        float wv[DR];
        #pragma unroll
        for (int j = 0; j < DR; j++) wv[j] = dtw[d*DR + j];
        float bb = dtb[d];
        float out[8];
        #pragma unroll
        for (int rr = 0; rr < 8; rr++) {
            float acc = bb;
            #pragma unroll
            for (int j = 0; j < DR; j++) acc = fmaf(sdt[rr][j], wv[j], acc);
            float e = __expf(-fabsf(acc));
            out[rr] = fmaxf(acc, 0.f) + __logf(1.f + e);
        }
        float4* pd = (float4*)&g_deltaT[((size_t)b*DI + d)*Wd + w0];
        pd[0] = make_float4(out[0],out[1],out[2],out[3]);
        pd[1] = make_float4(out[4],out[5],out[6],out[7]);
    }
}

// ---------------- scan phase A (transposed streams) ----------------
__global__ __launch_bounds__(128) void k_scanA(const float* __restrict__ A_log) {
    int gw = (blockIdx.x * blockDim.x + threadIdx.x) >> 5;
    int lane = threadIdx.x & 31;
    int chunk = gw & (NCHK-1);
    int dpair = (gw >> 4) & 255;
    int b = gw >> 12;
    int s = lane & 15, dch = lane >> 4;
    int dd = dpair*2 + dch;

    float Av = -expf(A_log[dd*DS + s]);
    size_t toff = (size_t)chunk * CLEN;
    const float* pd = g_deltaT + ((size_t)b*DI + dd)*Wd + toff;
    const float* pu = g_xsT    + ((size_t)b*DI + dd)*Wd + toff;
    const float* pB = g_dbc + ((size_t)b*Wd + toff)*48 + DR + s;

    float h = 0.f, sd = 0.f;
    #pragma unroll 4
    for (int t = 0; t < CLEN; t++) {
        float dc = pd[t];
        float uc = pu[t];
        float Bc = pB[(size_t)t*48];
        float dA = __expf(dc * Av);
        h = fmaf(dA, h, dc * Bc * uc);
        sd += dc;
    }
    size_t base = (size_t)(b*256 + dpair)*NCHK + chunk;
    g_hend[base*32 + lane] = h;
    if (s == 0) g_sumd[base*2 + dch] = sd;
}

// ---------------- scan phase B ----------------
__global__ __launch_bounds__(128) void k_scanB(const float* __restrict__ A_log) {
    int gw = (blockIdx.x * blockDim.x + threadIdx.x) >> 5;
    int lane = threadIdx.x & 31;
    int dpair = gw & 255;
    int b = gw >> 8;
    int s = lane & 15, dch = lane >> 4;
    int dd = dpair*2 + dch;

    float Av = -expf(A_log[dd*DS + s]);
    size_t base0 = (size_t)(b*256 + dpair)*NCHK;
    float H = 0.f;
    #pragma unroll
    for (int c = 0; c < NCHK; c++) {
        g_h0[(base0+c)*32 + lane] = H;
        float sd = g_sumd[(base0+c)*2 + dch];
        float he = g_hend[(base0+c)*32 + lane];
        H = fmaf(__expf(Av * sd), H, he);
    }
}

// ---------------- scan phase C: transposed streams, buffered yT stores ---------------
__global__ __launch_bounds__(128) void k_scanC(const float* __restrict__ A_log,
                                               const float* __restrict__ Dp) {
    int gw = (blockIdx.x * blockDim.x + threadIdx.x) >> 5;
    int lane = threadIdx.x & 31;
    int chunk = gw & (NCHK-1);
    int dpair = (gw >> 4) & 255;
    int b = gw >> 12;
    int s = lane & 15, dch = lane >> 4;
    int dd = dpair*2 + dch;

    float Av = -expf(A_log[dd*DS + s]);
    float Dpv = Dp[dd];
    size_t toff = (size_t)chunk * CLEN;
    const float* pd = g_deltaT + ((size_t)b*DI + dd)*Wd + toff;
    const float* pu = g_xsT    + ((size_t)b*DI + dd)*Wd + toff;
    const float* pg = g_gzT    + ((size_t)b*DI + dd)*Wd + toff;
    const float* pB = g_dbc + ((size_t)b*Wd + toff)*48 + DR + s;
    const float* pC = g_dbc + ((size_t)b*Wd + toff)*48 + DR + DS + s;
    float* py = g_yT + ((size_t)b*DI + dd)*Wd + toff;

    size_t base = (size_t)(b*256 + dpair)*NCHK + chunk;
    float hst = g_h0[base*32 + lane];
    float ybuf[8];

    #pragma unroll 8
    for (int t = 0; t < CLEN; t++) {
        float dc = pd[t];
        float uc = pu[t];
        float Bc = pB[(size_t)t*48];
        float Cc = pC[(size_t)t*48];
        float gz = pg[t];
        float dA = __expf(dc * Av);
        hst = fmaf(dA, hst, dc * Bc * uc);
        float yv = hst * Cc;
        yv += __shfl_xor_sync(0xffffffffu, yv, 8);
        yv += __shfl_xor_sync(0xffffffffu, yv, 4);
        yv += __shfl_xor_sync(0xffffffffu, yv, 2);
        yv += __shfl_xor_sync(0xffffffffu, yv, 1);
        ybuf[t & 7] = fmaf(uc, Dpv, yv) * gz;
        if ((t & 7) == 7 && s == 0) {
            float4* p = (float4*)&py[t - 7];
            p[0] = make_float4(ybuf[0], ybuf[1], ybuf[2], ybuf[3]);
            p[1] = make_float4(ybuf[4], ybuf[5], ybuf[6], ybuf[7]);
        }
    }
}

// ---------------- transpose + bf16-split: g_yT -> g_act3 ----------------
__global__ __launch_bounds__(256) void k_trcvt() {
    __shared__ float tile[32][33];
    int b = blockIdx.z;
    int d0 = blockIdx.y * 32, t0 = blockIdx.x * 32;
    int lr = threadIdx.x >> 5, lc = threadIdx.x & 31;
    #pragma unroll
    for (int p = 0; p < 4; p++) {
        int dl = p*8 + lr;
        tile[dl][lc] = g_yT[((size_t)b*DI + d0 + dl)*Wd + t0 + lc];
    }
    __syncthreads();
    #pragma unroll
    for (int p = 0; p < 4; p++) {
        int tl = p*8 + lr;
        float v = tile[lc][tl];
        __nv_bfloat16 hi = __float2bfloat16(v);
        __nv_bfloat16 lo = __float2bfloat16(v - __bfloat162float(hi));
        size_t row = ((size_t)b*Wd + t0 + tl) * (size_t)(3*DI);
        g_act3[row + d0 + lc] = hi;
        g_act3[row + DI + d0 + lc] = hi;
        g_act3[row + 2*DI + d0 + lc] = lo;
    }
}

// ---------------- host launch ----------------
extern "C" void kernel_launch(void* const* d_in, const int* in_sizes, int n_in,
                              void* d_out, int out_size) {
    const float* x         = (const float*)d_in[0];
    const float* emb_w     = (const float*)d_in[1];
    const float* emb_b     = (const float*)d_in[2];
    const float* in_proj_w = (const float*)d_in[3];
    const float* conv_w    = (const float*)d_in[4];
    const float* conv_b    = (const float*)d_in[5];
    const float* x_proj_w  = (const float*)d_in[6];
    const float* dt_proj_w = (const float*)d_in[7];
    const float* dt_proj_b = (const float*)d_in[8];
    const float* A_log     = (const float*)d_in[9];
    const float* Dp        = (const float*)d_in[10];
    const float* out_proj_w= (const float*)d_in[11];
    const float* norm_w    = (const float*)d_in[12];
    float* h = (float*)d_out;

    float *p_xz;
    __nv_bfloat16 *p_act3, *p_w3;
    cudaGetSymbolAddress((void**)&p_xz,   g_xz);
    cudaGetSymbolAddress((void**)&p_act3, g_act3);
    cudaGetSymbolAddress((void**)&p_w3,   g_w3);

    k_embed<<<NROW, DM>>>(x, emb_w, emb_b, h);

    for (int l = 0; l < 2; ++l) {
        const float* inw = in_proj_w + (size_t)l * (2*DI) * DM;
        const float* cw  = conv_w   + (size_t)l * DI * 4;
        const float* cb  = conv_b   + (size_t)l * DI;
        const float* xpw = x_proj_w + (size_t)l * 48 * DI;
        const float* dtw = dt_proj_w+ (size_t)l * DI * DR;
        const float* dtb = dt_proj_b+ (size_t)l * DI;
        const float* al  = A_log    + (size_t)l * DI * DS;
        const float* dp  = Dp       + (size_t)l * DI;
        const float* ow  = out_proj_w + (size_t)l * DM * DI;
        const float* nw  = norm_w   + (size_t)l * DM;

        // GEMM1: xz = rmsnorm(h) @ in_w^T
        k_rmscvt<<<NROW, DM>>>(h, nw, p_act3);
        k_cvt<<<((2*DI)*DM)/256, 256>>>(inw, p_w3, DM, 1);
        {
            dim3 grid((2*DI)/128, NROW/128);
            k_mgemm<128,false><<<grid, 256>>>(p_act3, p_w3, p_xz, 2*DI, 3*DM);
        }

        // conv+silu + xproj + dt + z-silu (fused, transposed outputs)
        k_xprojc<<<NROW/8, 256>>>(cw, cb, xpw, dtw, dtb);

        // 3-phase scan on [d][t] streams
        k_scanA<<<(Bq*256*NCHK*32)/128, 128>>>(al);
        k_scanB<<<(Bq*256*32)/128, 128>>>(al);
        k_scanC<<<(Bq*256*NCHK*32)/128, 128>>>(al, dp);

        // transpose + split y -> act3
        {
            dim3 grid(Wd/32, DI/32, Bq);
            k_trcvt<<<grid, 256>>>();
        }

        // GEMM2: h += y @ ow^T
        k_cvt<<<(DM*DI)/256, 256>>>(ow, p_w3, DI, 1);
        {
            dim3 grid(DM/64, NROW/128);
            k_mgemm<64,true><<<grid, 256>>>(p_act3, p_w3, h, DM, 3*DI);
        }
    }
}